// round 14
// baseline (speedup 1.0000x reference)
#include <cuda_runtime.h>
#include <cuda_bf16.h>
#include <math.h>
#include <stdint.h>

#define B_   32
#define C_   768
#define D_   512
#define NH_  4
#define HD_  192
#define FHW_ 576

// ---------------- device scratch (zero-init, no runtime allocation) ----------
__device__ float g_sq[32*4*192], g_sk[32*4*192];
__device__ float g_mu1[18432], g_rs1[18432];
__device__ float g_sum2[18432], g_sq2[18432];     // raw LN sums for out (atomic)
__device__ float g_rsumWo[768];
__device__ float g_out[32L*768*576];              // attn-block output fp32
__device__ __nv_bfloat16 g_qkb[32L*1536*576];     // q,k bf16 channel-major
__device__ __nv_bfloat16 g_wqkv[2304*768];
__device__ __nv_bfloat16 g_woimg[768*768];
__device__ __nv_bfloat16 g_woimg2[576*192];
__device__ __nv_bfloat16 g_wfc1[768*768];
__device__ __nv_bfloat16 g_wfc2[768*768];
__device__ __nv_bfloat16 g_lnimgT[32L*576*768];   // LN(img) pixel-major
__device__ __nv_bfloat16 g_v[32L*768*576];        // v bf16 channel-major
__device__ __nv_bfloat16 g_attn[128L*256*576];    // attn rows; rows 192..255 stay zero
__device__ __nv_bfloat16 g_imgT[32L*192*768];     // img transposed: [g][c]
__device__ __nv_bfloat16 g_T[32L*768*192];        // T = Wo @ img, row-major [o][g]
__device__ __nv_bfloat16 g_lnoutT[32L*576*768];   // LN(out) pixel-major
__device__ __nv_bfloat16 g_z1[32L*768*576];       // fc1 out channel-major
__device__ __nv_bfloat16 g_z2T[32L*576*768];      // dw+gelu pixel-major

// ---------------- fused txt layernorm + qkv sign factors ----------------------
__global__ void txt_k(const float* __restrict__ T, const float* __restrict__ gw,
                      const float* __restrict__ gb, const float* __restrict__ Wq) {
    int b = blockIdx.x, tid = threadIdx.x;
    __shared__ float t[512];
    __shared__ float red[16], mr[2];
    const float* row = T + (long)b * D_;
    float s = 0.f, ss = 0.f;
    for (int i = tid; i < D_; i += 256) { float v = row[i]; s += v; ss += v * v; }
    for (int o = 16; o; o >>= 1) { s += __shfl_down_sync(~0u, s, o); ss += __shfl_down_sync(~0u, ss, o); }
    int w = tid >> 5;
    if ((tid & 31) == 0) { red[w] = s; red[8 + w] = ss; }
    __syncthreads();
    if (tid == 0) {
        float S = 0.f, S2 = 0.f;
        for (int i = 0; i < 8; i++) { S += red[i]; S2 += red[8 + i]; }
        float m = S / D_, v = S2 / D_ - m * m;
        mr[0] = m; mr[1] = rsqrtf(v + 1e-5f);
    }
    __syncthreads();
    float m = mr[0], r = mr[1];
    for (int i = tid; i < D_; i += 256)
        t[i] = (row[i] - m) * r * gw[i] + gb[i];
    __syncthreads();
    #pragma unroll
    for (int j = 0; j < 6; j++) {
        int idx = j * 256 + tid;
        int n = idx / 384, rr = idx % 384, part = rr / 192, hd = rr % 192;
        const float* wp = Wq + (long)(n * 576 + part * 192 + hd) * 512;
        float acc = 0.f;
        #pragma unroll 8
        for (int k2 = 0; k2 < 512; k2++) acc += t[k2] * wp[k2];
        float sgn = acc / fmaxf(fabsf(acc), 1e-12f);
        if (part == 0) g_sq[(b * 4 + n) * 192 + hd] = sgn;
        else           g_sk[(b * 4 + n) * 192 + hd] = sgn;
    }
}

// rowsum of Wo + zero the atomic stats accumulators (re-zeroed every launch)
__global__ void rowsum_k(const float* __restrict__ W) {
    int gthread = blockIdx.x * 256 + threadIdx.x;   // 24576 threads
    if (gthread < 18432) { g_sum2[gthread] = 0.f; g_sq2[gthread] = 0.f; }
    int row = blockIdx.x * 8 + (threadIdx.x >> 5);
    int lane = threadIdx.x & 31;
    const float* p = W + (long)row * 768;
    float s = 0.f;
    for (int c = lane; c < 768; c += 32) s += p[c];
    for (int o = 16; o; o >>= 1) s += __shfl_down_sync(~0u, s, o);
    if (lane == 0) g_rsumWo[row] = s;
}

__global__ void castall_k(const float* __restrict__ w0, const float* __restrict__ w1,
                          const float* __restrict__ w2, const float* __restrict__ w3,
                          const float* __restrict__ w4) {
    long i4 = ((long)blockIdx.x * 256 + threadIdx.x) * 4;
    const float* src; __nv_bfloat16* dst; long off;
    if      (i4 < 1769472) { src = w0; dst = g_wqkv;   off = i4; }
    else if (i4 < 2359296) { src = w1; dst = g_woimg;  off = i4 - 1769472; }
    else if (i4 < 2469888) { src = w2; dst = g_woimg2; off = i4 - 2359296; }
    else if (i4 < 3059712) { src = w3; dst = g_wfc1;   off = i4 - 2469888; }
    else                   { src = w4; dst = g_wfc2;   off = i4 - 3059712; }
    float4 v = *(const float4*)(src + off);
    __nv_bfloat162 a, b;
    a.x = __float2bfloat16(v.x); a.y = __float2bfloat16(v.y);
    b.x = __float2bfloat16(v.z); b.y = __float2bfloat16(v.w);
    *(__nv_bfloat162*)(dst + off)     = a;
    *(__nv_bfloat162*)(dst + off + 2) = b;
}

// ---------------- per-pixel LN stats for img -----------------------------------
__global__ void stats_k(const float* __restrict__ X) {
    int gp = blockIdx.x * 32 + (threadIdx.x & 31);
    int grp = threadIdx.x >> 5;
    int b = gp / FHW_, p = gp % FHW_;
    const float* base = X + (long)b * C_ * FHW_ + p;
    float s = 0.f, ss = 0.f;
    for (int c = grp; c < C_; c += 8) { float v = base[(long)c * FHW_]; s += v; ss += v * v; }
    __shared__ float Ss[8][32], S2[8][32];
    Ss[grp][threadIdx.x & 31] = s; S2[grp][threadIdx.x & 31] = ss;
    __syncthreads();
    if (grp == 0) {
        for (int g = 1; g < 8; g++) { s += Ss[g][threadIdx.x & 31]; ss += S2[g][threadIdx.x & 31]; }
        float m = s / C_, v = ss / C_ - m * m;
        g_mu1[gp] = m; g_rs1[gp] = rsqrtf(v + 1e-6f);
    }
}

// SRC=0: img, stats from g_mu1/g_rs1.  SRC=1: g_out, stats from raw atomic sums.
template<int SRC>
__global__ void lnT_k(const float* __restrict__ Xext,
                      const float* __restrict__ w, const float* __restrict__ b) {
    const float* X  = (SRC == 0) ? Xext : g_out;
    __nv_bfloat16* T = (SRC == 0) ? g_lnimgT : g_lnoutT;
    int bz = blockIdx.z, n0 = blockIdx.x * 32, c0 = blockIdx.y * 64;
    __shared__ float t[64][33];
    const float* Xb = X + (long)bz * 442368;
    int nn = threadIdx.x & 31, cc = threadIdx.x >> 5;
    #pragma unroll
    for (int i = 0; i < 8; i++)
        t[cc + i * 8][nn] = Xb[(long)(c0 + cc + i * 8) * 576 + n0 + nn];
    __syncthreads();
    int c = threadIdx.x & 63, nn2 = threadIdx.x >> 6;
    #pragma unroll
    for (int i = 0; i < 8; i++) {
        int n = n0 + nn2 + i * 4;
        float m, r;
        if (SRC == 0) {
            m = g_mu1[bz * 576 + n]; r = g_rs1[bz * 576 + n];
        } else {
            float s = g_sum2[bz * 576 + n], q = g_sq2[bz * 576 + n];
            m = s * (1.f / 768.f);
            r = rsqrtf(q * (1.f / 768.f) - m * m + 1e-6f);
        }
        float v = (t[c][n - n0] - m) * r * w[c0 + c] + b[c0 + c];
        T[(long)bz * 442368 + (long)n * 768 + c0 + c] = __float2bfloat16(v);
    }
}

// ---------------- attention rows: warp-per-row, shuffle-only, bf162 -----------
__device__ __forceinline__ float wred(float v, int op) {
    #pragma unroll
    for (int o = 16; o; o >>= 1) {
        float t = __shfl_xor_sync(~0u, v, o);
        v = op ? fmaxf(v, t) : v + t;
    }
    return v;
}

__global__ void attn_k() {
    int gwarp = blockIdx.x * 8 + (threadIdx.x >> 5);
    int lane = threadIdx.x & 31;
    int hd = gwarp % 192, n = (gwarp / 192) % 4, b = gwarp / 768;
    const __nv_bfloat162* q2 = (const __nv_bfloat162*)(g_qkb + ((long)b * 1536 + n * 192 + hd) * 576);
    const __nv_bfloat162* k2 = q2 + (768L * 576) / 2;
    float q[18], k[18];
    float sumq = 0.f, sumk = 0.f;
    #pragma unroll
    for (int i = 0; i < 9; i++) {
        __nv_bfloat162 qv = q2[lane + 32 * i];
        __nv_bfloat162 kv = k2[lane + 32 * i];
        q[2*i]   = __bfloat162float(qv.x); q[2*i+1] = __bfloat162float(qv.y);
        k[2*i]   = __bfloat162float(kv.x); k[2*i+1] = __bfloat162float(kv.y);
        sumq += q[2*i]*q[2*i] + q[2*i+1]*q[2*i+1];
        sumk += k[2*i]*k[2*i] + k[2*i+1]*k[2*i+1];
    }
    sumq = wred(sumq, 0); sumk = wred(sumk, 0);
    float rq = 1.f / fmaxf(sqrtf(sumq), 1e-12f);
    float rk = 1.f / fmaxf(sqrtf(sumk), 1e-12f);
    float sgq = g_sq[(b * 4 + n) * 192 + hd];
    float sgk = g_sk[(b * 4 + n) * 192 + hd];
    float sa = sgq * rk, sc = sgk * rq;
    float m1 = -1e30f, m2 = -1e30f;
    #pragma unroll
    for (int i = 0; i < 18; i++) {
        m1 = fmaxf(m1, sa * k[i]);
        m2 = fmaxf(m2, sc * q[i]);
    }
    m1 = wred(m1, 1); m2 = wred(m2, 1);
    float e[18], f[18], S1 = 0.f, S2 = 0.f;
    #pragma unroll
    for (int i = 0; i < 18; i++) {
        e[i] = __expf(sa * k[i] - m1);
        f[i] = __expf(sc * q[i] - m2);
        S1 += e[i]; S2 += f[i];
    }
    S1 = wred(S1, 0); S2 = wred(S2, 0);
    float i1 = 1.f / S1, i2 = 1.f / S2;
    __nv_bfloat162* o2 = (__nv_bfloat162*)(g_attn + (long)(b * 4 + n) * 147456 + (long)hd * 576);
    #pragma unroll
    for (int i = 0; i < 9; i++) {
        __nv_bfloat162 v;
        v.x = __float2bfloat16(e[2*i]   * i1 + f[2*i]   * i2);
        v.y = __float2bfloat16(e[2*i+1] * i1 + f[2*i+1] * i2);
        o2[lane + 32 * i] = v;
    }
}

__global__ void dwgelu2_k(const float* __restrict__ Wd) {
    int blk = blockIdx.x;
    int b = blk / 96, cg = blk % 96;
    __shared__ float p[8][578];
    __shared__ __nv_bfloat16 ob[576][8];
    __shared__ float w[8][9];
    const __nv_bfloat16* Zb = g_z1 + ((long)b * 768 + cg * 8) * 576;
    for (int i = threadIdx.x; i < 8 * 576; i += 256)
        p[i / 576][i % 576] = __bfloat162float(Zb[i]);
    if (threadIdx.x < 72)
        w[threadIdx.x / 9][threadIdx.x % 9] = Wd[(cg * 8 + threadIdx.x / 9) * 9 + threadIdx.x % 9];
    __syncthreads();
    for (int i = threadIdx.x; i < 8 * 576; i += 256) {
        int ch = i & 7, pix = i >> 3;
        int y = pix / 24, x = pix % 24;
        float acc = 0.f;
        #pragma unroll
        for (int dy = -1; dy <= 1; dy++)
            #pragma unroll
            for (int dx = -1; dx <= 1; dx++) {
                int yy = y + dy, xx = x + dx;
                if (yy >= 0 && yy < 24 && xx >= 0 && xx < 24)
                    acc = fmaf(w[ch][(dy + 1) * 3 + dx + 1], p[ch][yy * 24 + xx], acc);
            }
        float g = 0.5f * acc * (1.f + erff(acc * 0.70710678118654752f));
        ob[pix][ch] = __float2bfloat16(g);
    }
    __syncthreads();
    __nv_bfloat16* Ob = g_z2T + (long)b * 442368 + cg * 8;
    for (int pix = threadIdx.x; pix < 576; pix += 256)
        *(uint4*)(Ob + (long)pix * 768) = *(uint4*)&ob[pix][0];
}

// ---------------- warp-MMA bf16 GEMM: BM=128, BN=96, BK=64, 3-stage -----------
#define ASTRIDE 144
#define STAGEB  32256

__device__ __forceinline__ uint32_t smem_u32(const void* p) {
    uint32_t a;
    asm("{ .reg .u64 t; cvta.to.shared.u64 t, %1; cvt.u32.u64 %0, t; }" : "=r"(a) : "l"(p));
    return a;
}
#define LDSM4(r0,r1,r2,r3,addr) \
    asm volatile("ldmatrix.sync.aligned.m8n8.x4.shared.b16 {%0,%1,%2,%3}, [%4];" \
        : "=r"(r0),"=r"(r1),"=r"(r2),"=r"(r3) : "r"(addr))
#define MMA16816(d,a,b0,b1) \
    asm volatile("mma.sync.aligned.m16n8k16.row.col.f32.bf16.bf16.f32 " \
        "{%0,%1,%2,%3},{%4,%5,%6,%7},{%8,%9},{%0,%1,%2,%3};" \
        : "+f"((d)[0]),"+f"((d)[1]),"+f"((d)[2]),"+f"((d)[3]) \
        : "r"((a)[0]),"r"((a)[1]),"r"((a)[2]),"r"((a)[3]),"r"(b0),"r"(b1))
#define CPA16(dst, src) \
    asm volatile("cp.async.cg.shared.global [%0], [%1], 16;" :: "r"(dst), "l"(src))
#define CP_COMMIT() asm volatile("cp.async.commit_group;")
#define CP_WAIT1()  asm volatile("cp.async.wait_group 1;")
#define CP_WAIT0()  asm volatile("cp.async.wait_group 0;")

template<int EPI>
__global__ void __launch_bounds__(256, 2) mm_gemm(
    const float* __restrict__ biasM, const float* __restrict__ biasN,
    const float* __restrict__ resExt, float* __restrict__ f32o)
{
    constexpr int K   = (EPI == 1) ? 576 : (EPI == 3) ? 192 : 768;
    constexpr int nkb = K / 64;
    constexpr long sAz = (EPI == 1) ? 147456 : (EPI == 3) ? 147456 : 0;
    constexpr long sBz = (EPI == 0) ? 442368 : (EPI == 1) ? 110592 :
                         (EPI == 2) ? 147456 : (EPI == 3) ? 0 : 442368;

    const __nv_bfloat16* Aop =
        (EPI == 0) ? g_wqkv : (EPI == 1) ? g_attn : (EPI == 2) ? g_woimg :
        (EPI == 3) ? g_T : (EPI == 4) ? g_wfc1 : g_wfc2;
    const __nv_bfloat16* Bop =
        (EPI == 0) ? g_lnimgT : (EPI == 1) ? g_v : (EPI == 2) ? g_imgT :
        (EPI == 3) ? g_woimg2 : (EPI == 4) ? g_lnoutT : g_z2T;

    extern __shared__ __align__(16) char sm[];
    __shared__ float s_sum[96], s_sq[96];
    uint32_t sbase = smem_u32(sm);

    int tid = threadIdx.x, lane = tid & 31, wid = tid >> 5;
    int wm = wid & 3, wn = wid >> 2;
    int z = blockIdx.z, m0 = blockIdx.y * 128, n0 = blockIdx.x * 96;
    const __nv_bfloat16* Ab = Aop + sAz * z + (long)m0 * K;
    const __nv_bfloat16* Bb = Bop + sBz * z + (long)n0 * K;

    float acc[2][6][4];
    #pragma unroll
    for (int i = 0; i < 2; i++)
        #pragma unroll
        for (int j = 0; j < 6; j++)
            #pragma unroll
            for (int k = 0; k < 4; k++) acc[i][j][k] = 0.f;

    auto load_stage = [&](int slot, int kblk) {
        uint32_t sd = sbase + slot * STAGEB;
        const __nv_bfloat16* Akp = Ab + kblk * 64;
        const __nv_bfloat16* Bkp = Bb + kblk * 64;
        #pragma unroll
        for (int it = 0; it < 7; it++) {
            int i = tid + it * 256;
            int row = i >> 3, ch = i & 7;
            const __nv_bfloat16* src = (row < 128)
                ? (Akp + (long)row * K + ch * 8)
                : (Bkp + (long)(row - 128) * K + ch * 8);
            CPA16(sd + row * ASTRIDE + ch * 16, src);
        }
    };

    auto ldfrag = [&](uint32_t abase, uint32_t bbase, int s,
                      uint32_t (&fa)[2][4], uint32_t (&fb)[3][4]) {
        #pragma unroll
        for (int mi = 0; mi < 2; mi++) {
            uint32_t addr = abase + (mi * 16 + (lane & 15)) * ASTRIDE
                          + s * 32 + (lane >> 4) * 16;
            LDSM4(fa[mi][0], fa[mi][1], fa[mi][2], fa[mi][3], addr);
        }
        #pragma unroll
        for (int j = 0; j < 3; j++) {
            int nrow = j * 16 + (lane & 7) + ((lane >> 4) & 1) * 8;
            uint32_t addr = bbase + nrow * ASTRIDE + s * 32 + ((lane >> 3) & 1) * 16;
            LDSM4(fb[j][0], fb[j][1], fb[j][2], fb[j][3], addr);
        }
    };
    auto domma = [&](uint32_t (&fa)[2][4], uint32_t (&fb)[3][4]) {
        #pragma unroll
        for (int mi = 0; mi < 2; mi++)
            #pragma unroll
            for (int ni = 0; ni < 6; ni++)
                MMA16816(acc[mi][ni], fa[mi], fb[ni >> 1][(ni & 1) * 2], fb[ni >> 1][(ni & 1) * 2 + 1]);
    };

    load_stage(0, 0); CP_COMMIT();
    load_stage(1, 1); CP_COMMIT();

    uint32_t fa0[2][4], fb0[3][4], fa1[2][4], fb1[3][4];

    for (int kb = 0; kb < nkb; kb++) {
        CP_WAIT1();
        __syncthreads();
        int nxt = kb + 2;
        if (nxt < nkb) load_stage(nxt % 3, nxt);
        CP_COMMIT();

        int buf = kb % 3;
        uint32_t abase = sbase + buf * STAGEB + (wm * 32) * ASTRIDE;
        uint32_t bbase = sbase + buf * STAGEB + 128 * ASTRIDE + (wn * 48) * ASTRIDE;
        ldfrag(abase, bbase, 0, fa0, fb0);
        ldfrag(abase, bbase, 1, fa1, fb1);
        domma(fa0, fb0);
        ldfrag(abase, bbase, 2, fa0, fb0);
        domma(fa1, fb1);
        ldfrag(abase, bbase, 3, fa1, fb1);
        domma(fa0, fb0);
        domma(fa1, fb1);
    }

    // ---------------- epilogue ----------------
    if (EPI == 1) {
        CP_WAIT0();
        __syncthreads();
        __nv_bfloat16* st = (__nv_bfloat16*)sm;
        #pragma unroll
        for (int mi = 0; mi < 2; mi++)
            #pragma unroll
            for (int ni = 0; ni < 6; ni++) {
                int cl = wn * 48 + ni * 8 + 2 * (lane & 3);
                #pragma unroll
                for (int h = 0; h < 2; h++) {
                    int rl = wm * 32 + mi * 16 + (lane >> 2) + h * 8;
                    st[cl * 136 + rl]       = __float2bfloat16(acc[mi][ni][h * 2]);
                    st[(cl + 1) * 136 + rl] = __float2bfloat16(acc[mi][ni][h * 2 + 1]);
                }
            }
        __syncthreads();
        int bz = z >> 2, nh = z & 3;
        int hvalid = (m0 == 0) ? 128 : 64;
        for (int task = tid; task < 96 * 16; task += 256) {
            int cc = task >> 4, h0 = (task & 15) * 8;
            if (h0 < hvalid) {
                uint4 v = *(uint4*)&st[cc * 136 + h0];
                long dst = (long)bz * 147456 + (long)(n0 + cc) * 768 + nh * 192 + m0 + h0;
                *(uint4*)(g_imgT + dst) = v;
            }
        }
        return;
    }

    if (EPI == 3) {
        if (tid < 96) { s_sum[tid] = 0.f; s_sq[tid] = 0.f; }
        __syncthreads();
    }

    const int mrow = m0 + wm * 32;
    const int ncol = n0 + wn * 48;
    #pragma unroll
    for (int mi = 0; mi < 2; mi++) {
        #pragma unroll
        for (int ni = 0; ni < 6; ni++) {
            int c = ncol + ni * 8 + 2 * (lane & 3);
            float ls0 = 0.f, lq0 = 0.f, ls1 = 0.f, lq1 = 0.f;
            #pragma unroll
            for (int h = 0; h < 2; h++) {
                int r = mrow + mi * 16 + (lane >> 2) + h * 8;
                float f0 = acc[mi][ni][h * 2], f1 = acc[mi][ni][h * 2 + 1];
                if (EPI == 0) {
                    __nv_bfloat162 v;
                    v.x = __float2bfloat16(f0); v.y = __float2bfloat16(f1);
                    if (r < 1536)
                        *(__nv_bfloat162*)(g_qkb + (long)z * 884736 + (long)r * 576 + c) = v;
                    else
                        *(__nv_bfloat162*)(g_v + (long)z * 442368 + (long)(r - 1536) * 576 + c) = v;
                } else if (EPI == 2) {
                    __nv_bfloat162 v;
                    v.x = __float2bfloat16(f0); v.y = __float2bfloat16(f1);
                    *(__nv_bfloat162*)(g_T + (long)z * 147456 + (long)r * 192 + c) = v;
                } else if (EPI == 3) {
                    long o = (long)z * 442368 + (long)r * 576 + c;
                    float bm = biasM[r], rsum = g_rsumWo[r];
                    float2 rv = *(const float2*)(resExt + o);
                    float v0 = f0 + bm + rsum * biasN[c] + rv.x;
                    float v1 = f1 + bm + rsum * biasN[c + 1] + rv.y;
                    float2 v = { v0, v1 };
                    *(float2*)(g_out + o) = v;
                    ls0 += v0; lq0 += v0 * v0;
                    ls1 += v1; lq1 += v1 * v1;
                } else if (EPI == 4) {
                    __nv_bfloat162 v;
                    v.x = __float2bfloat16(f0); v.y = __float2bfloat16(f1);
                    *(__nv_bfloat162*)(g_z1 + (long)z * 442368 + (long)r * 576 + c) = v;
                } else {
                    long o = (long)z * 442368 + (long)r * 576 + c;
                    float2 rv = *(const float2*)(g_out + o);
                    float2 v = { f0 + rv.x, f1 + rv.y };
                    *(float2*)(f32o + o) = v;
                }
            }
            if (EPI == 3) {
                int cl = c - n0;
                atomicAdd(&s_sum[cl], ls0); atomicAdd(&s_sq[cl], lq0);
                atomicAdd(&s_sum[cl + 1], ls1); atomicAdd(&s_sq[cl + 1], lq1);
            }
        }
    }
    if (EPI == 3) {
        __syncthreads();
        if (tid < 96) {
            atomicAdd(&g_sum2[z * 576 + n0 + tid], s_sum[tid]);
            atomicAdd(&g_sq2[z * 576 + n0 + tid], s_sq[tid]);
        }
    }
}

// ---------------- host launch --------------------------------------------------
extern "C" void kernel_launch(void* const* d_in, const int* in_sizes, int n_in,
                              void* d_out, int out_size) {
    const float* img    = (const float*)d_in[0];
    const float* txt    = (const float*)d_in[1];
    const float* fn_w   = (const float*)d_in[2];
    const float* fn_b   = (const float*)d_in[3];
    const float* gn_w   = (const float*)d_in[4];
    const float* gn_b   = (const float*)d_in[5];
    const float* qkv_img_w = (const float*)d_in[6];
    const float* qkv_txt_w = (const float*)d_in[7];
    const float* o_img_w   = (const float*)d_in[8];
    const float* o_img_b   = (const float*)d_in[9];
    const float* o_img2_w  = (const float*)d_in[10];
    const float* o_img2_b  = (const float*)d_in[11];
    const float* ffn_w  = (const float*)d_in[12];
    const float* ffn_b  = (const float*)d_in[13];
    const float* fc1_w  = (const float*)d_in[14];
    const float* dw_w   = (const float*)d_in[15];
    const float* fc2_w  = (const float*)d_in[16];
    float* out_p = (float*)d_out;

    const int SMEM = 3 * STAGEB;  // 96768
    cudaFuncSetAttribute(mm_gemm<0>, cudaFuncAttributeMaxDynamicSharedMemorySize, SMEM);
    cudaFuncSetAttribute(mm_gemm<1>, cudaFuncAttributeMaxDynamicSharedMemorySize, SMEM);
    cudaFuncSetAttribute(mm_gemm<2>, cudaFuncAttributeMaxDynamicSharedMemorySize, SMEM);
    cudaFuncSetAttribute(mm_gemm<3>, cudaFuncAttributeMaxDynamicSharedMemorySize, SMEM);
    cudaFuncSetAttribute(mm_gemm<4>, cudaFuncAttributeMaxDynamicSharedMemorySize, SMEM);
    cudaFuncSetAttribute(mm_gemm<5>, cudaFuncAttributeMaxDynamicSharedMemorySize, SMEM);

    castall_k<<<3564, 256>>>(qkv_img_w, o_img_w, o_img2_w, fc1_w, fc2_w);
    rowsum_k<<<96, 256>>>(o_img_w);
    txt_k<<<32, 256>>>(txt, gn_w, gn_b, qkv_txt_w);
    stats_k<<<(B_ * FHW_) / 32, 256>>>(img);
    lnT_k<0><<<dim3(18, 12, 32), 256>>>(img, fn_w, fn_b);

    // qkv projection: M=2304, N=576, K=768
    mm_gemm<0><<<dim3(6, 18, 32), 256, SMEM>>>(nullptr, nullptr, nullptr, nullptr);
    attn_k<<<3072, 256>>>();
    // (attn1+attn2) @ V^T -> imgT: M=256(pad), N=192, K=576, batch=128
    mm_gemm<1><<<dim3(2, 2, 128), 256, SMEM>>>(nullptr, nullptr, nullptr, nullptr);
    // T = Wo @ img^T: M=768, N=192, K=768
    mm_gemm<2><<<dim3(2, 6, 32), 256, SMEM>>>(nullptr, nullptr, nullptr, nullptr);
    // out = T @ W2^T + bO + rsumWo*b2 + img -> g_out (+LN stats via atomics)
    mm_gemm<3><<<dim3(6, 6, 32), 256, SMEM>>>(o_img_b, o_img2_b, img, nullptr);
    lnT_k<1><<<dim3(18, 12, 32), 256>>>(nullptr, ffn_w, ffn_b);
    // fc1: M=768, N=576, K=768
    mm_gemm<4><<<dim3(6, 6, 32), 256, SMEM>>>(nullptr, nullptr, nullptr, nullptr);
    dwgelu2_k<<<B_ * 96, 256>>>(dw_w);
    // fc2 + residual(g_out) -> d_out
    mm_gemm<5><<<dim3(6, 6, 32), 256, SMEM>>>(nullptr, nullptr, nullptr, out_p);
}

// round 15
// speedup vs baseline: 1.0887x; 1.0887x over previous
#include <cuda_runtime.h>
#include <cuda_bf16.h>
#include <math.h>
#include <stdint.h>

#define B_   32
#define C_   768
#define D_   512
#define NH_  4
#define HD_  192
#define FHW_ 576

// ---------------- device scratch (zero-init, no runtime allocation) ----------
__device__ float g_sq[32*4*192], g_sk[32*4*192];
__device__ float g_mu1[18432], g_rs1[18432], g_mu2[18432], g_rs2[18432];
__device__ float g_rsumWo[768];
__device__ float g_out[32L*768*576];              // attn-block output fp32
__device__ __nv_bfloat16 g_qkb[32L*1536*576];     // q,k bf16 channel-major
__device__ __nv_bfloat16 g_wqkv[2304*768];
__device__ __nv_bfloat16 g_woimg[768*768];
__device__ __nv_bfloat16 g_woimg2[576*192];
__device__ __nv_bfloat16 g_wfc1[768*768];
__device__ __nv_bfloat16 g_wfc2[768*768];
__device__ __nv_bfloat16 g_lnimgT[32L*576*768];   // LN(img) pixel-major
__device__ __nv_bfloat16 g_v[32L*768*576];        // v bf16 channel-major
__device__ __nv_bfloat16 g_attn[128L*256*576];    // attn rows; rows 192..255 stay zero
__device__ __nv_bfloat16 g_imgT[32L*192*768];     // img transposed: [g][c]
__device__ __nv_bfloat16 g_T[32L*768*192];        // T = Wo @ img, row-major [o][g]
__device__ __nv_bfloat16 g_lnoutT[32L*576*768];   // LN(out) pixel-major
__device__ __nv_bfloat16 g_z1[32L*768*576];       // fc1 out channel-major
__device__ __nv_bfloat16 g_z2T[32L*576*768];      // dw+gelu pixel-major

// ---------------- fused txt layernorm + qkv sign factors ----------------------
__global__ void txt_k(const float* __restrict__ T, const float* __restrict__ gw,
                      const float* __restrict__ gb, const float* __restrict__ Wq) {
    int b = blockIdx.x, tid = threadIdx.x;
    __shared__ float t[512];
    __shared__ float red[16], mr[2];
    const float* row = T + (long)b * D_;
    float s = 0.f, ss = 0.f;
    for (int i = tid; i < D_; i += 256) { float v = row[i]; s += v; ss += v * v; }
    for (int o = 16; o; o >>= 1) { s += __shfl_down_sync(~0u, s, o); ss += __shfl_down_sync(~0u, ss, o); }
    int w = tid >> 5;
    if ((tid & 31) == 0) { red[w] = s; red[8 + w] = ss; }
    __syncthreads();
    if (tid == 0) {
        float S = 0.f, S2 = 0.f;
        for (int i = 0; i < 8; i++) { S += red[i]; S2 += red[8 + i]; }
        float m = S / D_, v = S2 / D_ - m * m;
        mr[0] = m; mr[1] = rsqrtf(v + 1e-5f);
    }
    __syncthreads();
    float m = mr[0], r = mr[1];
    for (int i = tid; i < D_; i += 256)
        t[i] = (row[i] - m) * r * gw[i] + gb[i];
    __syncthreads();
    #pragma unroll
    for (int j = 0; j < 6; j++) {
        int idx = j * 256 + tid;
        int n = idx / 384, rr = idx % 384, part = rr / 192, hd = rr % 192;
        const float* wp = Wq + (long)(n * 576 + part * 192 + hd) * 512;
        float acc = 0.f;
        #pragma unroll 8
        for (int k2 = 0; k2 < 512; k2++) acc += t[k2] * wp[k2];
        float sgn = acc / fmaxf(fabsf(acc), 1e-12f);
        if (part == 0) g_sq[(b * 4 + n) * 192 + hd] = sgn;
        else           g_sk[(b * 4 + n) * 192 + hd] = sgn;
    }
}

__global__ void rowsum_k(const float* __restrict__ W) {
    int row = blockIdx.x * 8 + (threadIdx.x >> 5);
    int lane = threadIdx.x & 31;
    const float* p = W + (long)row * 768;
    float s = 0.f;
    for (int c = lane; c < 768; c += 32) s += p[c];
    for (int o = 16; o; o >>= 1) s += __shfl_down_sync(~0u, s, o);
    if (lane == 0) g_rsumWo[row] = s;
}

__global__ void castall_k(const float* __restrict__ w0, const float* __restrict__ w1,
                          const float* __restrict__ w2, const float* __restrict__ w3,
                          const float* __restrict__ w4) {
    long i4 = ((long)blockIdx.x * 256 + threadIdx.x) * 4;
    const float* src; __nv_bfloat16* dst; long off;
    if      (i4 < 1769472) { src = w0; dst = g_wqkv;   off = i4; }
    else if (i4 < 2359296) { src = w1; dst = g_woimg;  off = i4 - 1769472; }
    else if (i4 < 2469888) { src = w2; dst = g_woimg2; off = i4 - 2359296; }
    else if (i4 < 3059712) { src = w3; dst = g_wfc1;   off = i4 - 2469888; }
    else                   { src = w4; dst = g_wfc2;   off = i4 - 3059712; }
    float4 v = *(const float4*)(src + off);
    __nv_bfloat162 a, b;
    a.x = __float2bfloat16(v.x); a.y = __float2bfloat16(v.y);
    b.x = __float2bfloat16(v.z); b.y = __float2bfloat16(v.w);
    *(__nv_bfloat162*)(dst + off)     = a;
    *(__nv_bfloat162*)(dst + off + 2) = b;
}

// ---------------- per-pixel LN stats -------------------------------------------
template<int SRC>
__global__ void stats_k(const float* __restrict__ Xext) {
    const float* X = (SRC == 0) ? Xext : g_out;
    float* mu = (SRC == 0) ? g_mu1 : g_mu2;
    float* rs = (SRC == 0) ? g_rs1 : g_rs2;
    int gp = blockIdx.x * 32 + (threadIdx.x & 31);
    int grp = threadIdx.x >> 5;
    int b = gp / FHW_, p = gp % FHW_;
    const float* base = X + (long)b * C_ * FHW_ + p;
    float s = 0.f, ss = 0.f;
    for (int c = grp; c < C_; c += 8) { float v = base[(long)c * FHW_]; s += v; ss += v * v; }
    __shared__ float Ss[8][32], S2[8][32];
    Ss[grp][threadIdx.x & 31] = s; S2[grp][threadIdx.x & 31] = ss;
    __syncthreads();
    if (grp == 0) {
        for (int g = 1; g < 8; g++) { s += Ss[g][threadIdx.x & 31]; ss += S2[g][threadIdx.x & 31]; }
        float m = s / C_, v = ss / C_ - m * m;
        mu[gp] = m; rs[gp] = rsqrtf(v + 1e-6f);
    }
}

template<int SRC>
__global__ void lnT_k(const float* __restrict__ Xext,
                      const float* __restrict__ w, const float* __restrict__ b) {
    const float* X  = (SRC == 0) ? Xext : g_out;
    const float* mu = (SRC == 0) ? g_mu1 : g_mu2;
    const float* rs = (SRC == 0) ? g_rs1 : g_rs2;
    __nv_bfloat16* T = (SRC == 0) ? g_lnimgT : g_lnoutT;
    int bz = blockIdx.z, n0 = blockIdx.x * 32, c0 = blockIdx.y * 64;
    __shared__ float t[64][33];
    const float* Xb = X + (long)bz * 442368;
    int nn = threadIdx.x & 31, cc = threadIdx.x >> 5;
    #pragma unroll
    for (int i = 0; i < 8; i++)
        t[cc + i * 8][nn] = Xb[(long)(c0 + cc + i * 8) * 576 + n0 + nn];
    __syncthreads();
    int c = threadIdx.x & 63, nn2 = threadIdx.x >> 6;
    #pragma unroll
    for (int i = 0; i < 8; i++) {
        int n = n0 + nn2 + i * 4;
        float m = mu[bz * 576 + n], r = rs[bz * 576 + n];
        float v = (t[c][n - n0] - m) * r * w[c0 + c] + b[c0 + c];
        T[(long)bz * 442368 + (long)n * 768 + c0 + c] = __float2bfloat16(v);
    }
}

// ---------------- attention rows: warp-per-row, shuffle-only, bf162 -----------
__device__ __forceinline__ float wred(float v, int op) {
    #pragma unroll
    for (int o = 16; o; o >>= 1) {
        float t = __shfl_xor_sync(~0u, v, o);
        v = op ? fmaxf(v, t) : v + t;
    }
    return v;
}

__global__ void attn_k() {
    int gwarp = blockIdx.x * 8 + (threadIdx.x >> 5);
    int lane = threadIdx.x & 31;
    int hd = gwarp % 192, n = (gwarp / 192) % 4, b = gwarp / 768;
    const __nv_bfloat162* q2 = (const __nv_bfloat162*)(g_qkb + ((long)b * 1536 + n * 192 + hd) * 576);
    const __nv_bfloat162* k2 = q2 + (768L * 576) / 2;
    float q[18], k[18];
    float sumq = 0.f, sumk = 0.f;
    #pragma unroll
    for (int i = 0; i < 9; i++) {
        __nv_bfloat162 qv = q2[lane + 32 * i];
        __nv_bfloat162 kv = k2[lane + 32 * i];
        q[2*i]   = __bfloat162float(qv.x); q[2*i+1] = __bfloat162float(qv.y);
        k[2*i]   = __bfloat162float(kv.x); k[2*i+1] = __bfloat162float(kv.y);
        sumq += q[2*i]*q[2*i] + q[2*i+1]*q[2*i+1];
        sumk += k[2*i]*k[2*i] + k[2*i+1]*k[2*i+1];
    }
    sumq = wred(sumq, 0); sumk = wred(sumk, 0);
    float rq = 1.f / fmaxf(sqrtf(sumq), 1e-12f);
    float rk = 1.f / fmaxf(sqrtf(sumk), 1e-12f);
    float sgq = g_sq[(b * 4 + n) * 192 + hd];
    float sgk = g_sk[(b * 4 + n) * 192 + hd];
    float sa = sgq * rk, sc = sgk * rq;
    float m1 = -1e30f, m2 = -1e30f;
    #pragma unroll
    for (int i = 0; i < 18; i++) {
        m1 = fmaxf(m1, sa * k[i]);
        m2 = fmaxf(m2, sc * q[i]);
    }
    m1 = wred(m1, 1); m2 = wred(m2, 1);
    float e[18], f[18], S1 = 0.f, S2 = 0.f;
    #pragma unroll
    for (int i = 0; i < 18; i++) {
        e[i] = __expf(sa * k[i] - m1);
        f[i] = __expf(sc * q[i] - m2);
        S1 += e[i]; S2 += f[i];
    }
    S1 = wred(S1, 0); S2 = wred(S2, 0);
    float i1 = 1.f / S1, i2 = 1.f / S2;
    __nv_bfloat162* o2 = (__nv_bfloat162*)(g_attn + (long)(b * 4 + n) * 147456 + (long)hd * 576);
    #pragma unroll
    for (int i = 0; i < 9; i++) {
        __nv_bfloat162 v;
        v.x = __float2bfloat16(e[2*i]   * i1 + f[2*i]   * i2);
        v.y = __float2bfloat16(e[2*i+1] * i1 + f[2*i+1] * i2);
        o2[lane + 32 * i] = v;
    }
}

__global__ void dwgelu2_k(const float* __restrict__ Wd) {
    int blk = blockIdx.x;
    int b = blk / 96, cg = blk % 96;
    __shared__ float p[8][578];
    __shared__ __nv_bfloat16 ob[576][8];
    __shared__ float w[8][9];
    const __nv_bfloat16* Zb = g_z1 + ((long)b * 768 + cg * 8) * 576;
    for (int i = threadIdx.x; i < 8 * 576; i += 256)
        p[i / 576][i % 576] = __bfloat162float(Zb[i]);
    if (threadIdx.x < 72)
        w[threadIdx.x / 9][threadIdx.x % 9] = Wd[(cg * 8 + threadIdx.x / 9) * 9 + threadIdx.x % 9];
    __syncthreads();
    for (int i = threadIdx.x; i < 8 * 576; i += 256) {
        int ch = i & 7, pix = i >> 3;
        int y = pix / 24, x = pix % 24;
        float acc = 0.f;
        #pragma unroll
        for (int dy = -1; dy <= 1; dy++)
            #pragma unroll
            for (int dx = -1; dx <= 1; dx++) {
                int yy = y + dy, xx = x + dx;
                if (yy >= 0 && yy < 24 && xx >= 0 && xx < 24)
                    acc = fmaf(w[ch][(dy + 1) * 3 + dx + 1], p[ch][yy * 24 + xx], acc);
            }
        float g = 0.5f * acc * (1.f + erff(acc * 0.70710678118654752f));
        ob[pix][ch] = __float2bfloat16(g);
    }
    __syncthreads();
    __nv_bfloat16* Ob = g_z2T + (long)b * 442368 + cg * 8;
    for (int pix = threadIdx.x; pix < 576; pix += 256)
        *(uint4*)(Ob + (long)pix * 768) = *(uint4*)&ob[pix][0];
}

// ---------------- warp-MMA bf16 GEMM: BM=128, BN=96, BK=64, 3-stage -----------
// R13 mainloop: register-fragment ping-pong pipelining inside each kb step.
#define ASTRIDE 144
#define STAGEB  32256

__device__ __forceinline__ uint32_t smem_u32(const void* p) {
    uint32_t a;
    asm("{ .reg .u64 t; cvta.to.shared.u64 t, %1; cvt.u32.u64 %0, t; }" : "=r"(a) : "l"(p));
    return a;
}
#define LDSM4(r0,r1,r2,r3,addr) \
    asm volatile("ldmatrix.sync.aligned.m8n8.x4.shared.b16 {%0,%1,%2,%3}, [%4];" \
        : "=r"(r0),"=r"(r1),"=r"(r2),"=r"(r3) : "r"(addr))
#define MMA16816(d,a,b0,b1) \
    asm volatile("mma.sync.aligned.m16n8k16.row.col.f32.bf16.bf16.f32 " \
        "{%0,%1,%2,%3},{%4,%5,%6,%7},{%8,%9},{%0,%1,%2,%3};" \
        : "+f"((d)[0]),"+f"((d)[1]),"+f"((d)[2]),"+f"((d)[3]) \
        : "r"((a)[0]),"r"((a)[1]),"r"((a)[2]),"r"((a)[3]),"r"(b0),"r"(b1))
#define CPA16(dst, src) \
    asm volatile("cp.async.cg.shared.global [%0], [%1], 16;" :: "r"(dst), "l"(src))
#define CP_COMMIT() asm volatile("cp.async.commit_group;")
#define CP_WAIT1()  asm volatile("cp.async.wait_group 1;")
#define CP_WAIT0()  asm volatile("cp.async.wait_group 0;")

template<int EPI>
__global__ void __launch_bounds__(256, 2) mm_gemm(
    const float* __restrict__ biasM, const float* __restrict__ biasN,
    const float* __restrict__ resExt, float* __restrict__ f32o)
{
    constexpr int K   = (EPI == 1) ? 576 : (EPI == 3) ? 192 : 768;
    constexpr int nkb = K / 64;
    constexpr long sAz = (EPI == 1) ? 147456 : (EPI == 3) ? 147456 : 0;
    constexpr long sBz = (EPI == 0) ? 442368 : (EPI == 1) ? 110592 :
                         (EPI == 2) ? 147456 : (EPI == 3) ? 0 : 442368;

    const __nv_bfloat16* Aop =
        (EPI == 0) ? g_wqkv : (EPI == 1) ? g_attn : (EPI == 2) ? g_woimg :
        (EPI == 3) ? g_T : (EPI == 4) ? g_wfc1 : g_wfc2;
    const __nv_bfloat16* Bop =
        (EPI == 0) ? g_lnimgT : (EPI == 1) ? g_v : (EPI == 2) ? g_imgT :
        (EPI == 3) ? g_woimg2 : (EPI == 4) ? g_lnoutT : g_z2T;

    extern __shared__ __align__(16) char sm[];
    uint32_t sbase = smem_u32(sm);

    int tid = threadIdx.x, lane = tid & 31, wid = tid >> 5;
    int wm = wid & 3, wn = wid >> 2;
    int z = blockIdx.z, m0 = blockIdx.y * 128, n0 = blockIdx.x * 96;
    const __nv_bfloat16* Ab = Aop + sAz * z + (long)m0 * K;
    const __nv_bfloat16* Bb = Bop + sBz * z + (long)n0 * K;

    float acc[2][6][4];
    #pragma unroll
    for (int i = 0; i < 2; i++)
        #pragma unroll
        for (int j = 0; j < 6; j++)
            #pragma unroll
            for (int k = 0; k < 4; k++) acc[i][j][k] = 0.f;

    auto load_stage = [&](int slot, int kblk) {
        uint32_t sd = sbase + slot * STAGEB;
        const __nv_bfloat16* Akp = Ab + kblk * 64;
        const __nv_bfloat16* Bkp = Bb + kblk * 64;
        #pragma unroll
        for (int it = 0; it < 7; it++) {
            int i = tid + it * 256;
            int row = i >> 3, ch = i & 7;
            const __nv_bfloat16* src = (row < 128)
                ? (Akp + (long)row * K + ch * 8)
                : (Bkp + (long)(row - 128) * K + ch * 8);
            CPA16(sd + row * ASTRIDE + ch * 16, src);
        }
    };

    auto ldfrag = [&](uint32_t abase, uint32_t bbase, int s,
                      uint32_t (&fa)[2][4], uint32_t (&fb)[3][4]) {
        #pragma unroll
        for (int mi = 0; mi < 2; mi++) {
            uint32_t addr = abase + (mi * 16 + (lane & 15)) * ASTRIDE
                          + s * 32 + (lane >> 4) * 16;
            LDSM4(fa[mi][0], fa[mi][1], fa[mi][2], fa[mi][3], addr);
        }
        #pragma unroll
        for (int j = 0; j < 3; j++) {
            int nrow = j * 16 + (lane & 7) + ((lane >> 4) & 1) * 8;
            uint32_t addr = bbase + nrow * ASTRIDE + s * 32 + ((lane >> 3) & 1) * 16;
            LDSM4(fb[j][0], fb[j][1], fb[j][2], fb[j][3], addr);
        }
    };
    auto domma = [&](uint32_t (&fa)[2][4], uint32_t (&fb)[3][4]) {
        #pragma unroll
        for (int mi = 0; mi < 2; mi++)
            #pragma unroll
            for (int ni = 0; ni < 6; ni++)
                MMA16816(acc[mi][ni], fa[mi], fb[ni >> 1][(ni & 1) * 2], fb[ni >> 1][(ni & 1) * 2 + 1]);
    };

    load_stage(0, 0); CP_COMMIT();
    load_stage(1, 1); CP_COMMIT();

    uint32_t fa0[2][4], fb0[3][4], fa1[2][4], fb1[3][4];

    for (int kb = 0; kb < nkb; kb++) {
        CP_WAIT1();
        __syncthreads();
        int nxt = kb + 2;
        if (nxt < nkb) load_stage(nxt % 3, nxt);
        CP_COMMIT();

        int buf = kb % 3;
        uint32_t abase = sbase + buf * STAGEB + (wm * 32) * ASTRIDE;
        uint32_t bbase = sbase + buf * STAGEB + 128 * ASTRIDE + (wn * 48) * ASTRIDE;
        ldfrag(abase, bbase, 0, fa0, fb0);
        ldfrag(abase, bbase, 1, fa1, fb1);
        domma(fa0, fb0);
        ldfrag(abase, bbase, 2, fa0, fb0);
        domma(fa1, fb1);
        ldfrag(abase, bbase, 3, fa1, fb1);
        domma(fa0, fb0);
        domma(fa1, fb1);
    }

    // ---------------- epilogue ----------------
    if (EPI == 1) {
        CP_WAIT0();
        __syncthreads();
        __nv_bfloat16* st = (__nv_bfloat16*)sm;
        #pragma unroll
        for (int mi = 0; mi < 2; mi++)
            #pragma unroll
            for (int ni = 0; ni < 6; ni++) {
                int cl = wn * 48 + ni * 8 + 2 * (lane & 3);
                #pragma unroll
                for (int h = 0; h < 2; h++) {
                    int rl = wm * 32 + mi * 16 + (lane >> 2) + h * 8;
                    st[cl * 136 + rl]       = __float2bfloat16(acc[mi][ni][h * 2]);
                    st[(cl + 1) * 136 + rl] = __float2bfloat16(acc[mi][ni][h * 2 + 1]);
                }
            }
        __syncthreads();
        int bz = z >> 2, nh = z & 3;
        int hvalid = (m0 == 0) ? 128 : 64;
        for (int task = tid; task < 96 * 16; task += 256) {
            int cc = task >> 4, h0 = (task & 15) * 8;
            if (h0 < hvalid) {
                uint4 v = *(uint4*)&st[cc * 136 + h0];
                long dst = (long)bz * 147456 + (long)(n0 + cc) * 768 + nh * 192 + m0 + h0;
                *(uint4*)(g_imgT + dst) = v;
            }
        }
        return;
    }

    const int mrow = m0 + wm * 32;
    const int ncol = n0 + wn * 48;
    #pragma unroll
    for (int mi = 0; mi < 2; mi++) {
        #pragma unroll
        for (int ni = 0; ni < 6; ni++) {
            int c = ncol + ni * 8 + 2 * (lane & 3);
            #pragma unroll
            for (int h = 0; h < 2; h++) {
                int r = mrow + mi * 16 + (lane >> 2) + h * 8;
                float f0 = acc[mi][ni][h * 2], f1 = acc[mi][ni][h * 2 + 1];
                if (EPI == 0) {
                    __nv_bfloat162 v;
                    v.x = __float2bfloat16(f0); v.y = __float2bfloat16(f1);
                    if (r < 1536)
                        *(__nv_bfloat162*)(g_qkb + (long)z * 884736 + (long)r * 576 + c) = v;
                    else
                        *(__nv_bfloat162*)(g_v + (long)z * 442368 + (long)(r - 1536) * 576 + c) = v;
                } else if (EPI == 2) {
                    __nv_bfloat162 v;
                    v.x = __float2bfloat16(f0); v.y = __float2bfloat16(f1);
                    *(__nv_bfloat162*)(g_T + (long)z * 147456 + (long)r * 192 + c) = v;
                } else if (EPI == 3) {
                    long o = (long)z * 442368 + (long)r * 576 + c;
                    float bm = biasM[r], rsum = g_rsumWo[r];
                    float2 rv = *(const float2*)(resExt + o);
                    float2 v = { f0 + bm + rsum * biasN[c] + rv.x,
                                 f1 + bm + rsum * biasN[c + 1] + rv.y };
                    *(float2*)(g_out + o) = v;
                } else if (EPI == 4) {
                    __nv_bfloat162 v;
                    v.x = __float2bfloat16(f0); v.y = __float2bfloat16(f1);
                    *(__nv_bfloat162*)(g_z1 + (long)z * 442368 + (long)r * 576 + c) = v;
                } else {
                    long o = (long)z * 442368 + (long)r * 576 + c;
                    float2 rv = *(const float2*)(g_out + o);
                    float2 v = { f0 + rv.x, f1 + rv.y };
                    *(float2*)(f32o + o) = v;
                }
            }
        }
    }
}

// ---------------- host launch --------------------------------------------------
extern "C" void kernel_launch(void* const* d_in, const int* in_sizes, int n_in,
                              void* d_out, int out_size) {
    const float* img    = (const float*)d_in[0];
    const float* txt    = (const float*)d_in[1];
    const float* fn_w   = (const float*)d_in[2];
    const float* fn_b   = (const float*)d_in[3];
    const float* gn_w   = (const float*)d_in[4];
    const float* gn_b   = (const float*)d_in[5];
    const float* qkv_img_w = (const float*)d_in[6];
    const float* qkv_txt_w = (const float*)d_in[7];
    const float* o_img_w   = (const float*)d_in[8];
    const float* o_img_b   = (const float*)d_in[9];
    const float* o_img2_w  = (const float*)d_in[10];
    const float* o_img2_b  = (const float*)d_in[11];
    const float* ffn_w  = (const float*)d_in[12];
    const float* ffn_b  = (const float*)d_in[13];
    const float* fc1_w  = (const float*)d_in[14];
    const float* dw_w   = (const float*)d_in[15];
    const float* fc2_w  = (const float*)d_in[16];
    float* out_p = (float*)d_out;

    const int SMEM = 3 * STAGEB;  // 96768
    cudaFuncSetAttribute(mm_gemm<0>, cudaFuncAttributeMaxDynamicSharedMemorySize, SMEM);
    cudaFuncSetAttribute(mm_gemm<1>, cudaFuncAttributeMaxDynamicSharedMemorySize, SMEM);
    cudaFuncSetAttribute(mm_gemm<2>, cudaFuncAttributeMaxDynamicSharedMemorySize, SMEM);
    cudaFuncSetAttribute(mm_gemm<3>, cudaFuncAttributeMaxDynamicSharedMemorySize, SMEM);
    cudaFuncSetAttribute(mm_gemm<4>, cudaFuncAttributeMaxDynamicSharedMemorySize, SMEM);
    cudaFuncSetAttribute(mm_gemm<5>, cudaFuncAttributeMaxDynamicSharedMemorySize, SMEM);

    castall_k<<<3564, 256>>>(qkv_img_w, o_img_w, o_img2_w, fc1_w, fc2_w);
    rowsum_k<<<96, 256>>>(o_img_w);
    txt_k<<<32, 256>>>(txt, gn_w, gn_b, qkv_txt_w);
    stats_k<0><<<(B_ * FHW_) / 32, 256>>>(img);
    lnT_k<0><<<dim3(18, 12, 32), 256>>>(img, fn_w, fn_b);

    // qkv projection: M=2304, N=576, K=768
    mm_gemm<0><<<dim3(6, 18, 32), 256, SMEM>>>(nullptr, nullptr, nullptr, nullptr);
    attn_k<<<3072, 256>>>();
    // (attn1+attn2) @ V^T -> imgT: M=256(pad), N=192, K=576, batch=128
    mm_gemm<1><<<dim3(2, 2, 128), 256, SMEM>>>(nullptr, nullptr, nullptr, nullptr);
    // T = Wo @ img^T: M=768, N=192, K=768
    mm_gemm<2><<<dim3(2, 6, 32), 256, SMEM>>>(nullptr, nullptr, nullptr, nullptr);
    // out = T @ W2^T + bO + rsumWo*b2 + img: M=768, N=576, K=192
    mm_gemm<3><<<dim3(6, 6, 32), 256, SMEM>>>(o_img_b, o_img2_b, img, nullptr);
    stats_k<1><<<(B_ * FHW_) / 32, 256>>>(nullptr);
    lnT_k<1><<<dim3(18, 12, 32), 256>>>(nullptr, ffn_w, ffn_b);
    // fc1: M=768, N=576, K=768
    mm_gemm<4><<<dim3(6, 6, 32), 256, SMEM>>>(nullptr, nullptr, nullptr, nullptr);
    dwgelu2_k<<<B_ * 96, 256>>>(dw_w);
    // fc2 + residual(g_out) -> d_out
    mm_gemm<5><<<dim3(6, 6, 32), 256, SMEM>>>(nullptr, nullptr, nullptr, out_p);
}

// round 16
// speedup vs baseline: 1.0991x; 1.0096x over previous
#include <cuda_runtime.h>
#include <cuda_bf16.h>
#include <math.h>
#include <stdint.h>

#define B_   32
#define C_   768
#define D_   512
#define NH_  4
#define HD_  192
#define FHW_ 576

// ---------------- device scratch (zero-init, no runtime allocation) ----------
__device__ float g_sq[32*4*192], g_sk[32*4*192];
__device__ float g_rsumWo[768];
__device__ float g_out[32L*768*576];              // attn-block output fp32
__device__ __nv_bfloat16 g_qkb[32L*1536*576];     // q,k bf16 channel-major
__device__ __nv_bfloat16 g_wqkv[2304*768];
__device__ __nv_bfloat16 g_woimg[768*768];
__device__ __nv_bfloat16 g_woimg2[576*192];
__device__ __nv_bfloat16 g_wfc1[768*768];
__device__ __nv_bfloat16 g_wfc2[768*768];
__device__ __nv_bfloat16 g_lnimgT[32L*576*768];   // LN(img) pixel-major
__device__ __nv_bfloat16 g_v[32L*768*576];        // v bf16 channel-major
__device__ __nv_bfloat16 g_attn[128L*256*576];    // attn rows; rows 192..255 stay zero
__device__ __nv_bfloat16 g_imgT[32L*192*768];     // img transposed: [g][c]
__device__ __nv_bfloat16 g_T[32L*768*192];        // T = Wo @ img, row-major [o][g]
__device__ __nv_bfloat16 g_lnoutT[32L*576*768];   // LN(out) pixel-major
__device__ __nv_bfloat16 g_z1[32L*768*576];       // fc1 out channel-major
__device__ __nv_bfloat16 g_z2T[32L*576*768];      // dw+gelu pixel-major

// ---------------- fused txt layernorm + qkv sign factors ----------------------
__global__ void txt_k(const float* __restrict__ T, const float* __restrict__ gw,
                      const float* __restrict__ gb, const float* __restrict__ Wq) {
    int b = blockIdx.x, tid = threadIdx.x;
    __shared__ float t[512];
    __shared__ float red[16], mr[2];
    const float* row = T + (long)b * D_;
    float s = 0.f, ss = 0.f;
    for (int i = tid; i < D_; i += 256) { float v = row[i]; s += v; ss += v * v; }
    for (int o = 16; o; o >>= 1) { s += __shfl_down_sync(~0u, s, o); ss += __shfl_down_sync(~0u, ss, o); }
    int w = tid >> 5;
    if ((tid & 31) == 0) { red[w] = s; red[8 + w] = ss; }
    __syncthreads();
    if (tid == 0) {
        float S = 0.f, S2 = 0.f;
        for (int i = 0; i < 8; i++) { S += red[i]; S2 += red[8 + i]; }
        float m = S / D_, v = S2 / D_ - m * m;
        mr[0] = m; mr[1] = rsqrtf(v + 1e-5f);
    }
    __syncthreads();
    float m = mr[0], r = mr[1];
    for (int i = tid; i < D_; i += 256)
        t[i] = (row[i] - m) * r * gw[i] + gb[i];
    __syncthreads();
    #pragma unroll
    for (int j = 0; j < 6; j++) {
        int idx = j * 256 + tid;
        int n = idx / 384, rr = idx % 384, part = rr / 192, hd = rr % 192;
        const float* wp = Wq + (long)(n * 576 + part * 192 + hd) * 512;
        float acc = 0.f;
        #pragma unroll 8
        for (int k2 = 0; k2 < 512; k2++) acc += t[k2] * wp[k2];
        float sgn = acc / fmaxf(fabsf(acc), 1e-12f);
        if (part == 0) g_sq[(b * 4 + n) * 192 + hd] = sgn;
        else           g_sk[(b * 4 + n) * 192 + hd] = sgn;
    }
}

__global__ void rowsum_k(const float* __restrict__ W) {
    int row = blockIdx.x * 8 + (threadIdx.x >> 5);
    int lane = threadIdx.x & 31;
    const float* p = W + (long)row * 768;
    float s = 0.f;
    for (int c = lane; c < 768; c += 32) s += p[c];
    for (int o = 16; o; o >>= 1) s += __shfl_down_sync(~0u, s, o);
    if (lane == 0) g_rsumWo[row] = s;
}

__global__ void castall_k(const float* __restrict__ w0, const float* __restrict__ w1,
                          const float* __restrict__ w2, const float* __restrict__ w3,
                          const float* __restrict__ w4) {
    long i4 = ((long)blockIdx.x * 256 + threadIdx.x) * 4;
    const float* src; __nv_bfloat16* dst; long off;
    if      (i4 < 1769472) { src = w0; dst = g_wqkv;   off = i4; }
    else if (i4 < 2359296) { src = w1; dst = g_woimg;  off = i4 - 1769472; }
    else if (i4 < 2469888) { src = w2; dst = g_woimg2; off = i4 - 2359296; }
    else if (i4 < 3059712) { src = w3; dst = g_wfc1;   off = i4 - 2469888; }
    else                   { src = w4; dst = g_wfc2;   off = i4 - 3059712; }
    float4 v = *(const float4*)(src + off);
    __nv_bfloat162 a, b;
    a.x = __float2bfloat16(v.x); a.y = __float2bfloat16(v.y);
    b.x = __float2bfloat16(v.z); b.y = __float2bfloat16(v.w);
    *(__nv_bfloat162*)(dst + off)     = a;
    *(__nv_bfloat162*)(dst + off + 2) = b;
}

// ---------------- fused per-pixel LN stats + normalize + transpose ------------
// Pass 1 streams the 32px x 768ch strip for stats (DRAM); pass 2 re-reads it
// tile-by-tile (L2-hot) to normalize+transpose. smem ~11 KB -> full occupancy.
template<int SRC>
__global__ void lnfT_k(const float* __restrict__ Xext,
                       const float* __restrict__ w, const float* __restrict__ b) {
    const float* X = (SRC == 0) ? Xext : g_out;
    __nv_bfloat16* T = (SRC == 0) ? g_lnimgT : g_lnoutT;
    int bz = blockIdx.y, px0 = blockIdx.x * 32;
    const float* Xb = X + (long)bz * 442368;
    __shared__ float muS[32], rsS[32];
    __shared__ float Ss[8][32], S2[8][32];
    __shared__ float t[64][33];
    int lane = threadIdx.x & 31, grp = threadIdx.x >> 5;
    // phase 1: per-pixel stats over 768 channels
    float s = 0.f, ss = 0.f;
    for (int c = grp; c < 768; c += 8) {
        float v = Xb[(long)c * 576 + px0 + lane];
        s += v; ss += v * v;
    }
    Ss[grp][lane] = s; S2[grp][lane] = ss;
    __syncthreads();
    if (grp == 0) {
        for (int g = 1; g < 8; g++) { s += Ss[g][lane]; ss += S2[g][lane]; }
        float m = s / 768.f, v = ss / 768.f - m * m;
        muS[lane] = m; rsS[lane] = rsqrtf(v + 1e-6f);
    }
    __syncthreads();
    // phase 2: normalize + transpose, 12 channel-blocks of 64
    int nn = threadIdx.x & 31, cc = threadIdx.x >> 5;
    int c = threadIdx.x & 63, nn2 = threadIdx.x >> 6;
    for (int c0 = 0; c0 < 768; c0 += 64) {
        #pragma unroll
        for (int i = 0; i < 8; i++)
            t[cc + i * 8][nn] = Xb[(long)(c0 + cc + i * 8) * 576 + px0 + nn];
        __syncthreads();
        float wc = w[c0 + c], bc = b[c0 + c];
        #pragma unroll
        for (int i = 0; i < 8; i++) {
            int p = nn2 + i * 4;
            float v = (t[c][p] - muS[p]) * rsS[p] * wc + bc;
            T[(long)bz * 442368 + (long)(px0 + p) * 768 + c0 + c] = __float2bfloat16(v);
        }
        __syncthreads();
    }
}

// ---------------- attention rows: warp-per-row, shuffle-only, bf162 -----------
__device__ __forceinline__ float wred(float v, int op) {
    #pragma unroll
    for (int o = 16; o; o >>= 1) {
        float t = __shfl_xor_sync(~0u, v, o);
        v = op ? fmaxf(v, t) : v + t;
    }
    return v;
}

__global__ void attn_k() {
    int gwarp = blockIdx.x * 8 + (threadIdx.x >> 5);
    int lane = threadIdx.x & 31;
    int hd = gwarp % 192, n = (gwarp / 192) % 4, b = gwarp / 768;
    const __nv_bfloat162* q2 = (const __nv_bfloat162*)(g_qkb + ((long)b * 1536 + n * 192 + hd) * 576);
    const __nv_bfloat162* k2 = q2 + (768L * 576) / 2;
    float q[18], k[18];
    float sumq = 0.f, sumk = 0.f;
    #pragma unroll
    for (int i = 0; i < 9; i++) {
        __nv_bfloat162 qv = q2[lane + 32 * i];
        __nv_bfloat162 kv = k2[lane + 32 * i];
        q[2*i]   = __bfloat162float(qv.x); q[2*i+1] = __bfloat162float(qv.y);
        k[2*i]   = __bfloat162float(kv.x); k[2*i+1] = __bfloat162float(kv.y);
        sumq += q[2*i]*q[2*i] + q[2*i+1]*q[2*i+1];
        sumk += k[2*i]*k[2*i] + k[2*i+1]*k[2*i+1];
    }
    sumq = wred(sumq, 0); sumk = wred(sumk, 0);
    float rq = 1.f / fmaxf(sqrtf(sumq), 1e-12f);
    float rk = 1.f / fmaxf(sqrtf(sumk), 1e-12f);
    float sgq = g_sq[(b * 4 + n) * 192 + hd];
    float sgk = g_sk[(b * 4 + n) * 192 + hd];
    float sa = sgq * rk, sc = sgk * rq;
    float m1 = -1e30f, m2 = -1e30f;
    #pragma unroll
    for (int i = 0; i < 18; i++) {
        m1 = fmaxf(m1, sa * k[i]);
        m2 = fmaxf(m2, sc * q[i]);
    }
    m1 = wred(m1, 1); m2 = wred(m2, 1);
    float e[18], f[18], S1 = 0.f, S2 = 0.f;
    #pragma unroll
    for (int i = 0; i < 18; i++) {
        e[i] = __expf(sa * k[i] - m1);
        f[i] = __expf(sc * q[i] - m2);
        S1 += e[i]; S2 += f[i];
    }
    S1 = wred(S1, 0); S2 = wred(S2, 0);
    float i1 = 1.f / S1, i2 = 1.f / S2;
    __nv_bfloat162* o2 = (__nv_bfloat162*)(g_attn + (long)(b * 4 + n) * 147456 + (long)hd * 576);
    #pragma unroll
    for (int i = 0; i < 9; i++) {
        __nv_bfloat162 v;
        v.x = __float2bfloat16(e[2*i]   * i1 + f[2*i]   * i2);
        v.y = __float2bfloat16(e[2*i+1] * i1 + f[2*i+1] * i2);
        o2[lane + 32 * i] = v;
    }
}

__global__ void dwgelu2_k(const float* __restrict__ Wd) {
    int blk = blockIdx.x;
    int b = blk / 96, cg = blk % 96;
    __shared__ float p[8][578];
    __shared__ __nv_bfloat16 ob[576][8];
    __shared__ float w[8][9];
    const __nv_bfloat16* Zb = g_z1 + ((long)b * 768 + cg * 8) * 576;
    for (int i = threadIdx.x; i < 8 * 576; i += 256)
        p[i / 576][i % 576] = __bfloat162float(Zb[i]);
    if (threadIdx.x < 72)
        w[threadIdx.x / 9][threadIdx.x % 9] = Wd[(cg * 8 + threadIdx.x / 9) * 9 + threadIdx.x % 9];
    __syncthreads();
    for (int i = threadIdx.x; i < 8 * 576; i += 256) {
        int ch = i & 7, pix = i >> 3;
        int y = pix / 24, x = pix % 24;
        float acc = 0.f;
        #pragma unroll
        for (int dy = -1; dy <= 1; dy++)
            #pragma unroll
            for (int dx = -1; dx <= 1; dx++) {
                int yy = y + dy, xx = x + dx;
                if (yy >= 0 && yy < 24 && xx >= 0 && xx < 24)
                    acc = fmaf(w[ch][(dy + 1) * 3 + dx + 1], p[ch][yy * 24 + xx], acc);
            }
        float g = 0.5f * acc * (1.f + erff(acc * 0.70710678118654752f));
        ob[pix][ch] = __float2bfloat16(g);
    }
    __syncthreads();
    __nv_bfloat16* Ob = g_z2T + (long)b * 442368 + cg * 8;
    for (int pix = threadIdx.x; pix < 576; pix += 256)
        *(uint4*)(Ob + (long)pix * 768) = *(uint4*)&ob[pix][0];
}

// ---------------- warp-MMA bf16 GEMM: BM=128, BN=96, BK=64, 3-stage -----------
#define ASTRIDE 144
#define STAGEB  32256

__device__ __forceinline__ uint32_t smem_u32(const void* p) {
    uint32_t a;
    asm("{ .reg .u64 t; cvta.to.shared.u64 t, %1; cvt.u32.u64 %0, t; }" : "=r"(a) : "l"(p));
    return a;
}
#define LDSM4(r0,r1,r2,r3,addr) \
    asm volatile("ldmatrix.sync.aligned.m8n8.x4.shared.b16 {%0,%1,%2,%3}, [%4];" \
        : "=r"(r0),"=r"(r1),"=r"(r2),"=r"(r3) : "r"(addr))
#define MMA16816(d,a,b0,b1) \
    asm volatile("mma.sync.aligned.m16n8k16.row.col.f32.bf16.bf16.f32 " \
        "{%0,%1,%2,%3},{%4,%5,%6,%7},{%8,%9},{%0,%1,%2,%3};" \
        : "+f"((d)[0]),"+f"((d)[1]),"+f"((d)[2]),"+f"((d)[3]) \
        : "r"((a)[0]),"r"((a)[1]),"r"((a)[2]),"r"((a)[3]),"r"(b0),"r"(b1))
#define CPA16(dst, src) \
    asm volatile("cp.async.cg.shared.global [%0], [%1], 16;" :: "r"(dst), "l"(src))
#define CP_COMMIT() asm volatile("cp.async.commit_group;")
#define CP_WAIT1()  asm volatile("cp.async.wait_group 1;")
#define CP_WAIT0()  asm volatile("cp.async.wait_group 0;")

template<int EPI>
__global__ void __launch_bounds__(256, 2) mm_gemm(
    const float* __restrict__ biasM, const float* __restrict__ biasN,
    const float* __restrict__ resExt, float* __restrict__ f32o)
{
    constexpr int K   = (EPI == 1) ? 576 : (EPI == 3) ? 192 : 768;
    constexpr int nkb = K / 64;
    constexpr long sAz = (EPI == 1) ? 147456 : (EPI == 3) ? 147456 : 0;
    constexpr long sBz = (EPI == 0) ? 442368 : (EPI == 1) ? 110592 :
                         (EPI == 2) ? 147456 : (EPI == 3) ? 0 : 442368;

    const __nv_bfloat16* Aop =
        (EPI == 0) ? g_wqkv : (EPI == 1) ? g_attn : (EPI == 2) ? g_woimg :
        (EPI == 3) ? g_T : (EPI == 4) ? g_wfc1 : g_wfc2;
    const __nv_bfloat16* Bop =
        (EPI == 0) ? g_lnimgT : (EPI == 1) ? g_v : (EPI == 2) ? g_imgT :
        (EPI == 3) ? g_woimg2 : (EPI == 4) ? g_lnoutT : g_z2T;

    extern __shared__ __align__(16) char sm[];
    uint32_t sbase = smem_u32(sm);

    int tid = threadIdx.x, lane = tid & 31, wid = tid >> 5;
    int wm = wid & 3, wn = wid >> 2;
    int z = blockIdx.z, m0 = blockIdx.y * 128, n0 = blockIdx.x * 96;
    const __nv_bfloat16* Ab = Aop + sAz * z + (long)m0 * K;
    const __nv_bfloat16* Bb = Bop + sBz * z + (long)n0 * K;

    float acc[2][6][4];
    #pragma unroll
    for (int i = 0; i < 2; i++)
        #pragma unroll
        for (int j = 0; j < 6; j++)
            #pragma unroll
            for (int k = 0; k < 4; k++) acc[i][j][k] = 0.f;

    auto load_stage = [&](int slot, int kblk) {
        uint32_t sd = sbase + slot * STAGEB;
        const __nv_bfloat16* Akp = Ab + kblk * 64;
        const __nv_bfloat16* Bkp = Bb + kblk * 64;
        #pragma unroll
        for (int it = 0; it < 7; it++) {
            int i = tid + it * 256;
            int row = i >> 3, ch = i & 7;
            const __nv_bfloat16* src = (row < 128)
                ? (Akp + (long)row * K + ch * 8)
                : (Bkp + (long)(row - 128) * K + ch * 8);
            CPA16(sd + row * ASTRIDE + ch * 16, src);
        }
    };

    auto ldfrag = [&](uint32_t abase, uint32_t bbase, int s,
                      uint32_t (&fa)[2][4], uint32_t (&fb)[3][4]) {
        #pragma unroll
        for (int mi = 0; mi < 2; mi++) {
            uint32_t addr = abase + (mi * 16 + (lane & 15)) * ASTRIDE
                          + s * 32 + (lane >> 4) * 16;
            LDSM4(fa[mi][0], fa[mi][1], fa[mi][2], fa[mi][3], addr);
        }
        #pragma unroll
        for (int j = 0; j < 3; j++) {
            int nrow = j * 16 + (lane & 7) + ((lane >> 4) & 1) * 8;
            uint32_t addr = bbase + nrow * ASTRIDE + s * 32 + ((lane >> 3) & 1) * 16;
            LDSM4(fb[j][0], fb[j][1], fb[j][2], fb[j][3], addr);
        }
    };
    auto domma = [&](uint32_t (&fa)[2][4], uint32_t (&fb)[3][4]) {
        #pragma unroll
        for (int mi = 0; mi < 2; mi++)
            #pragma unroll
            for (int ni = 0; ni < 6; ni++)
                MMA16816(acc[mi][ni], fa[mi], fb[ni >> 1][(ni & 1) * 2], fb[ni >> 1][(ni & 1) * 2 + 1]);
    };

    load_stage(0, 0); CP_COMMIT();
    load_stage(1, 1); CP_COMMIT();

    uint32_t fa0[2][4], fb0[3][4], fa1[2][4], fb1[3][4];

    for (int kb = 0; kb < nkb; kb++) {
        CP_WAIT1();
        __syncthreads();
        int nxt = kb + 2;
        if (nxt < nkb) load_stage(nxt % 3, nxt);
        CP_COMMIT();

        int buf = kb % 3;
        uint32_t abase = sbase + buf * STAGEB + (wm * 32) * ASTRIDE;
        uint32_t bbase = sbase + buf * STAGEB + 128 * ASTRIDE + (wn * 48) * ASTRIDE;
        ldfrag(abase, bbase, 0, fa0, fb0);
        ldfrag(abase, bbase, 1, fa1, fb1);
        domma(fa0, fb0);
        ldfrag(abase, bbase, 2, fa0, fb0);
        domma(fa1, fb1);
        ldfrag(abase, bbase, 3, fa1, fb1);
        domma(fa0, fb0);
        domma(fa1, fb1);
    }

    // ---------------- epilogue ----------------
    if (EPI == 1) {
        CP_WAIT0();
        __syncthreads();
        __nv_bfloat16* st = (__nv_bfloat16*)sm;
        #pragma unroll
        for (int mi = 0; mi < 2; mi++)
            #pragma unroll
            for (int ni = 0; ni < 6; ni++) {
                int cl = wn * 48 + ni * 8 + 2 * (lane & 3);
                #pragma unroll
                for (int h = 0; h < 2; h++) {
                    int rl = wm * 32 + mi * 16 + (lane >> 2) + h * 8;
                    st[cl * 136 + rl]       = __float2bfloat16(acc[mi][ni][h * 2]);
                    st[(cl + 1) * 136 + rl] = __float2bfloat16(acc[mi][ni][h * 2 + 1]);
                }
            }
        __syncthreads();
        int bz = z >> 2, nh = z & 3;
        int hvalid = (m0 == 0) ? 128 : 64;
        for (int task = tid; task < 96 * 16; task += 256) {
            int cc = task >> 4, h0 = (task & 15) * 8;
            if (h0 < hvalid) {
                uint4 v = *(uint4*)&st[cc * 136 + h0];
                long dst = (long)bz * 147456 + (long)(n0 + cc) * 768 + nh * 192 + m0 + h0;
                *(uint4*)(g_imgT + dst) = v;
            }
        }
        return;
    }

    const int mrow = m0 + wm * 32;
    const int ncol = n0 + wn * 48;
    #pragma unroll
    for (int mi = 0; mi < 2; mi++) {
        #pragma unroll
        for (int ni = 0; ni < 6; ni++) {
            int c = ncol + ni * 8 + 2 * (lane & 3);
            #pragma unroll
            for (int h = 0; h < 2; h++) {
                int r = mrow + mi * 16 + (lane >> 2) + h * 8;
                float f0 = acc[mi][ni][h * 2], f1 = acc[mi][ni][h * 2 + 1];
                if (EPI == 0) {
                    __nv_bfloat162 v;
                    v.x = __float2bfloat16(f0); v.y = __float2bfloat16(f1);
                    if (r < 1536)
                        *(__nv_bfloat162*)(g_qkb + (long)z * 884736 + (long)r * 576 + c) = v;
                    else
                        *(__nv_bfloat162*)(g_v + (long)z * 442368 + (long)(r - 1536) * 576 + c) = v;
                } else if (EPI == 2) {
                    __nv_bfloat162 v;
                    v.x = __float2bfloat16(f0); v.y = __float2bfloat16(f1);
                    *(__nv_bfloat162*)(g_T + (long)z * 147456 + (long)r * 192 + c) = v;
                } else if (EPI == 3) {
                    long o = (long)z * 442368 + (long)r * 576 + c;
                    float bm = biasM[r], rsum = g_rsumWo[r];
                    float2 rv = *(const float2*)(resExt + o);
                    float2 v = { f0 + bm + rsum * biasN[c] + rv.x,
                                 f1 + bm + rsum * biasN[c + 1] + rv.y };
                    *(float2*)(g_out + o) = v;
                } else if (EPI == 4) {
                    __nv_bfloat162 v;
                    v.x = __float2bfloat16(f0); v.y = __float2bfloat16(f1);
                    *(__nv_bfloat162*)(g_z1 + (long)z * 442368 + (long)r * 576 + c) = v;
                } else {
                    long o = (long)z * 442368 + (long)r * 576 + c;
                    float2 rv = *(const float2*)(g_out + o);
                    float2 v = { f0 + rv.x, f1 + rv.y };
                    *(float2*)(f32o + o) = v;
                }
            }
        }
    }
}

// ---------------- host launch --------------------------------------------------
extern "C" void kernel_launch(void* const* d_in, const int* in_sizes, int n_in,
                              void* d_out, int out_size) {
    const float* img    = (const float*)d_in[0];
    const float* txt    = (const float*)d_in[1];
    const float* fn_w   = (const float*)d_in[2];
    const float* fn_b   = (const float*)d_in[3];
    const float* gn_w   = (const float*)d_in[4];
    const float* gn_b   = (const float*)d_in[5];
    const float* qkv_img_w = (const float*)d_in[6];
    const float* qkv_txt_w = (const float*)d_in[7];
    const float* o_img_w   = (const float*)d_in[8];
    const float* o_img_b   = (const float*)d_in[9];
    const float* o_img2_w  = (const float*)d_in[10];
    const float* o_img2_b  = (const float*)d_in[11];
    const float* ffn_w  = (const float*)d_in[12];
    const float* ffn_b  = (const float*)d_in[13];
    const float* fc1_w  = (const float*)d_in[14];
    const float* dw_w   = (const float*)d_in[15];
    const float* fc2_w  = (const float*)d_in[16];
    float* out_p = (float*)d_out;

    const int SMEM = 3 * STAGEB;  // 96768
    cudaFuncSetAttribute(mm_gemm<0>, cudaFuncAttributeMaxDynamicSharedMemorySize, SMEM);
    cudaFuncSetAttribute(mm_gemm<1>, cudaFuncAttributeMaxDynamicSharedMemorySize, SMEM);
    cudaFuncSetAttribute(mm_gemm<2>, cudaFuncAttributeMaxDynamicSharedMemorySize, SMEM);
    cudaFuncSetAttribute(mm_gemm<3>, cudaFuncAttributeMaxDynamicSharedMemorySize, SMEM);
    cudaFuncSetAttribute(mm_gemm<4>, cudaFuncAttributeMaxDynamicSharedMemorySize, SMEM);
    cudaFuncSetAttribute(mm_gemm<5>, cudaFuncAttributeMaxDynamicSharedMemorySize, SMEM);

    castall_k<<<3564, 256>>>(qkv_img_w, o_img_w, o_img2_w, fc1_w, fc2_w);
    rowsum_k<<<96, 256>>>(o_img_w);
    txt_k<<<32, 256>>>(txt, gn_w, gn_b, qkv_txt_w);
    lnfT_k<0><<<dim3(18, 32), 256>>>(img, fn_w, fn_b);

    // qkv projection: M=2304, N=576, K=768
    mm_gemm<0><<<dim3(6, 18, 32), 256, SMEM>>>(nullptr, nullptr, nullptr, nullptr);
    attn_k<<<3072, 256>>>();
    // (attn1+attn2) @ V^T -> imgT: M=256(pad), N=192, K=576, batch=128
    mm_gemm<1><<<dim3(2, 2, 128), 256, SMEM>>>(nullptr, nullptr, nullptr, nullptr);
    // T = Wo @ img^T: M=768, N=192, K=768
    mm_gemm<2><<<dim3(2, 6, 32), 256, SMEM>>>(nullptr, nullptr, nullptr, nullptr);
    // out = T @ W2^T + bO + rsumWo*b2 + img: M=768, N=576, K=192
    mm_gemm<3><<<dim3(6, 6, 32), 256, SMEM>>>(o_img_b, o_img2_b, img, nullptr);
    lnfT_k<1><<<dim3(18, 32), 256>>>(nullptr, ffn_w, ffn_b);
    // fc1: M=768, N=576, K=768
    mm_gemm<4><<<dim3(6, 6, 32), 256, SMEM>>>(nullptr, nullptr, nullptr, nullptr);
    dwgelu2_k<<<B_ * 96, 256>>>(dw_w);
    // fc2 + residual(g_out) -> d_out
    mm_gemm<5><<<dim3(6, 6, 32), 256, SMEM>>>(nullptr, nullptr, nullptr, out_p);
}

// round 17
// speedup vs baseline: 1.1031x; 1.0036x over previous
#include <cuda_runtime.h>
#include <cuda_bf16.h>
#include <math.h>
#include <stdint.h>

#define B_   32
#define C_   768
#define D_   512
#define NH_  4
#define HD_  192
#define FHW_ 576

// ---------------- device scratch (zero-init, no runtime allocation) ----------
__device__ float g_sq[32*4*192], g_sk[32*4*192];
__device__ float g_rsumWo[768];
__device__ float g_out[32L*768*576];              // attn-block output fp32
__device__ __nv_bfloat16 g_qkb[32L*1536*576];     // q,k bf16 channel-major
__device__ __nv_bfloat16 g_wqkv[2304*768];
__device__ __nv_bfloat16 g_woimg[768*768];
__device__ __nv_bfloat16 g_woimg2[576*192];
__device__ __nv_bfloat16 g_wfc1[768*768];
__device__ __nv_bfloat16 g_wfc2[768*768];
__device__ __nv_bfloat16 g_lnimgT[32L*576*768];   // LN(img) pixel-major
__device__ __nv_bfloat16 g_v[32L*768*576];        // v bf16 channel-major
__device__ __nv_bfloat16 g_attn[128L*256*576];    // attn rows; rows 192..255 stay zero
__device__ __nv_bfloat16 g_imgT[32L*192*768];     // img transposed: [g][c]
__device__ __nv_bfloat16 g_T[32L*768*192];        // T = Wo @ img, row-major [o][g]
__device__ __nv_bfloat16 g_lnoutT[32L*576*768];   // LN(out) pixel-major
__device__ __nv_bfloat16 g_z1[32L*768*576];       // fc1 out channel-major
__device__ __nv_bfloat16 g_z2T[32L*576*768];      // dw+gelu pixel-major

// ---------------- fused txt layernorm + qkv sign factors ----------------------
__global__ void txt_k(const float* __restrict__ T, const float* __restrict__ gw,
                      const float* __restrict__ gb, const float* __restrict__ Wq) {
    int b = blockIdx.x, tid = threadIdx.x;
    __shared__ float t[512];
    __shared__ float red[16], mr[2];
    const float* row = T + (long)b * D_;
    float s = 0.f, ss = 0.f;
    for (int i = tid; i < D_; i += 256) { float v = row[i]; s += v; ss += v * v; }
    for (int o = 16; o; o >>= 1) { s += __shfl_down_sync(~0u, s, o); ss += __shfl_down_sync(~0u, ss, o); }
    int w = tid >> 5;
    if ((tid & 31) == 0) { red[w] = s; red[8 + w] = ss; }
    __syncthreads();
    if (tid == 0) {
        float S = 0.f, S2 = 0.f;
        for (int i = 0; i < 8; i++) { S += red[i]; S2 += red[8 + i]; }
        float m = S / D_, v = S2 / D_ - m * m;
        mr[0] = m; mr[1] = rsqrtf(v + 1e-5f);
    }
    __syncthreads();
    float m = mr[0], r = mr[1];
    for (int i = tid; i < D_; i += 256)
        t[i] = (row[i] - m) * r * gw[i] + gb[i];
    __syncthreads();
    #pragma unroll
    for (int j = 0; j < 6; j++) {
        int idx = j * 256 + tid;
        int n = idx / 384, rr = idx % 384, part = rr / 192, hd = rr % 192;
        const float* wp = Wq + (long)(n * 576 + part * 192 + hd) * 512;
        float acc = 0.f;
        #pragma unroll 8
        for (int k2 = 0; k2 < 512; k2++) acc += t[k2] * wp[k2];
        float sgn = acc / fmaxf(fabsf(acc), 1e-12f);
        if (part == 0) g_sq[(b * 4 + n) * 192 + hd] = sgn;
        else           g_sk[(b * 4 + n) * 192 + hd] = sgn;
    }
}

__global__ void rowsum_k(const float* __restrict__ W) {
    int row = blockIdx.x * 8 + (threadIdx.x >> 5);
    int lane = threadIdx.x & 31;
    const float* p = W + (long)row * 768;
    float s = 0.f;
    for (int c = lane; c < 768; c += 32) s += p[c];
    for (int o = 16; o; o >>= 1) s += __shfl_down_sync(~0u, s, o);
    if (lane == 0) g_rsumWo[row] = s;
}

__global__ void castall_k(const float* __restrict__ w0, const float* __restrict__ w1,
                          const float* __restrict__ w2, const float* __restrict__ w3,
                          const float* __restrict__ w4) {
    long i4 = ((long)blockIdx.x * 256 + threadIdx.x) * 4;
    const float* src; __nv_bfloat16* dst; long off;
    if      (i4 < 1769472) { src = w0; dst = g_wqkv;   off = i4; }
    else if (i4 < 2359296) { src = w1; dst = g_woimg;  off = i4 - 1769472; }
    else if (i4 < 2469888) { src = w2; dst = g_woimg2; off = i4 - 2359296; }
    else if (i4 < 3059712) { src = w3; dst = g_wfc1;   off = i4 - 2469888; }
    else                   { src = w4; dst = g_wfc2;   off = i4 - 3059712; }
    float4 v = *(const float4*)(src + off);
    __nv_bfloat162 a, b;
    a.x = __float2bfloat16(v.x); a.y = __float2bfloat16(v.y);
    b.x = __float2bfloat16(v.z); b.y = __float2bfloat16(v.w);
    *(__nv_bfloat162*)(dst + off)     = a;
    *(__nv_bfloat162*)(dst + off + 2) = b;
}

// ---------------- fused per-pixel LN stats + normalize + transpose ------------
template<int SRC>
__global__ void lnfT_k(const float* __restrict__ Xext,
                       const float* __restrict__ w, const float* __restrict__ b) {
    const float* X = (SRC == 0) ? Xext : g_out;
    __nv_bfloat16* T = (SRC == 0) ? g_lnimgT : g_lnoutT;
    int bz = blockIdx.y, px0 = blockIdx.x * 32;
    const float* Xb = X + (long)bz * 442368;
    __shared__ float muS[32], rsS[32];
    __shared__ float Ss[8][32], S2[8][32];
    __shared__ float t[64][33];
    int lane = threadIdx.x & 31, grp = threadIdx.x >> 5;
    float s = 0.f, ss = 0.f;
    for (int c = grp; c < 768; c += 8) {
        float v = Xb[(long)c * 576 + px0 + lane];
        s += v; ss += v * v;
    }
    Ss[grp][lane] = s; S2[grp][lane] = ss;
    __syncthreads();
    if (grp == 0) {
        for (int g = 1; g < 8; g++) { s += Ss[g][lane]; ss += S2[g][lane]; }
        float m = s / 768.f, v = ss / 768.f - m * m;
        muS[lane] = m; rsS[lane] = rsqrtf(v + 1e-6f);
    }
    __syncthreads();
    int nn = threadIdx.x & 31, cc = threadIdx.x >> 5;
    int c = threadIdx.x & 63, nn2 = threadIdx.x >> 6;
    for (int c0 = 0; c0 < 768; c0 += 64) {
        #pragma unroll
        for (int i = 0; i < 8; i++)
            t[cc + i * 8][nn] = Xb[(long)(c0 + cc + i * 8) * 576 + px0 + nn];
        __syncthreads();
        float wc = w[c0 + c], bc = b[c0 + c];
        #pragma unroll
        for (int i = 0; i < 8; i++) {
            int p = nn2 + i * 4;
            float v = (t[c][p] - muS[p]) * rsS[p] * wc + bc;
            T[(long)bz * 442368 + (long)(px0 + p) * 768 + c0 + c] = __float2bfloat16(v);
        }
        __syncthreads();
    }
}

// ---------------- attention rows: warp-per-row, shuffle-only, bf162 -----------
__device__ __forceinline__ float wred(float v, int op) {
    #pragma unroll
    for (int o = 16; o; o >>= 1) {
        float t = __shfl_xor_sync(~0u, v, o);
        v = op ? fmaxf(v, t) : v + t;
    }
    return v;
}

__global__ void attn_k() {
    int gwarp = blockIdx.x * 8 + (threadIdx.x >> 5);
    int lane = threadIdx.x & 31;
    int hd = gwarp % 192, n = (gwarp / 192) % 4, b = gwarp / 768;
    const __nv_bfloat162* q2 = (const __nv_bfloat162*)(g_qkb + ((long)b * 1536 + n * 192 + hd) * 576);
    const __nv_bfloat162* k2 = q2 + (768L * 576) / 2;
    float q[18], k[18];
    float sumq = 0.f, sumk = 0.f;
    #pragma unroll
    for (int i = 0; i < 9; i++) {
        __nv_bfloat162 qv = q2[lane + 32 * i];
        __nv_bfloat162 kv = k2[lane + 32 * i];
        q[2*i]   = __bfloat162float(qv.x); q[2*i+1] = __bfloat162float(qv.y);
        k[2*i]   = __bfloat162float(kv.x); k[2*i+1] = __bfloat162float(kv.y);
        sumq += q[2*i]*q[2*i] + q[2*i+1]*q[2*i+1];
        sumk += k[2*i]*k[2*i] + k[2*i+1]*k[2*i+1];
    }
    sumq = wred(sumq, 0); sumk = wred(sumk, 0);
    float rq = 1.f / fmaxf(sqrtf(sumq), 1e-12f);
    float rk = 1.f / fmaxf(sqrtf(sumk), 1e-12f);
    float sgq = g_sq[(b * 4 + n) * 192 + hd];
    float sgk = g_sk[(b * 4 + n) * 192 + hd];
    float sa = sgq * rk, sc = sgk * rq;
    float m1 = -1e30f, m2 = -1e30f;
    #pragma unroll
    for (int i = 0; i < 18; i++) {
        m1 = fmaxf(m1, sa * k[i]);
        m2 = fmaxf(m2, sc * q[i]);
    }
    m1 = wred(m1, 1); m2 = wred(m2, 1);
    float e[18], f[18], S1 = 0.f, S2 = 0.f;
    #pragma unroll
    for (int i = 0; i < 18; i++) {
        e[i] = __expf(sa * k[i] - m1);
        f[i] = __expf(sc * q[i] - m2);
        S1 += e[i]; S2 += f[i];
    }
    S1 = wred(S1, 0); S2 = wred(S2, 0);
    float i1 = 1.f / S1, i2 = 1.f / S2;
    __nv_bfloat162* o2 = (__nv_bfloat162*)(g_attn + (long)(b * 4 + n) * 147456 + (long)hd * 576);
    #pragma unroll
    for (int i = 0; i < 9; i++) {
        __nv_bfloat162 v;
        v.x = __float2bfloat16(e[2*i]   * i1 + f[2*i]   * i2);
        v.y = __float2bfloat16(e[2*i+1] * i1 + f[2*i+1] * i2);
        o2[lane + 32 * i] = v;
    }
}

__global__ void dwgelu2_k(const float* __restrict__ Wd) {
    int blk = blockIdx.x;
    int b = blk / 96, cg = blk % 96;
    __shared__ float p[8][578];
    __shared__ __nv_bfloat16 ob[576][8];
    __shared__ float w[8][9];
    const __nv_bfloat16* Zb = g_z1 + ((long)b * 768 + cg * 8) * 576;
    for (int i = threadIdx.x; i < 8 * 576; i += 256)
        p[i / 576][i % 576] = __bfloat162float(Zb[i]);
    if (threadIdx.x < 72)
        w[threadIdx.x / 9][threadIdx.x % 9] = Wd[(cg * 8 + threadIdx.x / 9) * 9 + threadIdx.x % 9];
    __syncthreads();
    for (int i = threadIdx.x; i < 8 * 576; i += 256) {
        int ch = i & 7, pix = i >> 3;
        int y = pix / 24, x = pix % 24;
        float acc = 0.f;
        #pragma unroll
        for (int dy = -1; dy <= 1; dy++)
            #pragma unroll
            for (int dx = -1; dx <= 1; dx++) {
                int yy = y + dy, xx = x + dx;
                if (yy >= 0 && yy < 24 && xx >= 0 && xx < 24)
                    acc = fmaf(w[ch][(dy + 1) * 3 + dx + 1], p[ch][yy * 24 + xx], acc);
            }
        float g = 0.5f * acc * (1.f + erff(acc * 0.70710678118654752f));
        ob[pix][ch] = __float2bfloat16(g);
    }
    __syncthreads();
    __nv_bfloat16* Ob = g_z2T + (long)b * 442368 + cg * 8;
    for (int pix = threadIdx.x; pix < 576; pix += 256)
        *(uint4*)(Ob + (long)pix * 768) = *(uint4*)&ob[pix][0];
}

// ---------------- warp-MMA bf16 GEMM: BM=128, BN=96, BK=64, 3-buffer ----------
// R17: cross-barrier software pipelining — s3 fragment MMAs held past the
// wait/sync so post-barrier LDSM latency hides behind them.
#define ASTRIDE 144
#define STAGEB  32256

__device__ __forceinline__ uint32_t smem_u32(const void* p) {
    uint32_t a;
    asm("{ .reg .u64 t; cvta.to.shared.u64 t, %1; cvt.u32.u64 %0, t; }" : "=r"(a) : "l"(p));
    return a;
}
#define LDSM4(r0,r1,r2,r3,addr) \
    asm volatile("ldmatrix.sync.aligned.m8n8.x4.shared.b16 {%0,%1,%2,%3}, [%4];" \
        : "=r"(r0),"=r"(r1),"=r"(r2),"=r"(r3) : "r"(addr))
#define MMA16816(d,a,b0,b1) \
    asm volatile("mma.sync.aligned.m16n8k16.row.col.f32.bf16.bf16.f32 " \
        "{%0,%1,%2,%3},{%4,%5,%6,%7},{%8,%9},{%0,%1,%2,%3};" \
        : "+f"((d)[0]),"+f"((d)[1]),"+f"((d)[2]),"+f"((d)[3]) \
        : "r"((a)[0]),"r"((a)[1]),"r"((a)[2]),"r"((a)[3]),"r"(b0),"r"(b1))
#define CPA16(dst, src) \
    asm volatile("cp.async.cg.shared.global [%0], [%1], 16;" :: "r"(dst), "l"(src))
#define CP_COMMIT() asm volatile("cp.async.commit_group;")
#define CP_WAIT1()  asm volatile("cp.async.wait_group 1;")
#define CP_WAIT0()  asm volatile("cp.async.wait_group 0;")

template<int EPI>
__global__ void __launch_bounds__(256, 2) mm_gemm(
    const float* __restrict__ biasM, const float* __restrict__ biasN,
    const float* __restrict__ resExt, float* __restrict__ f32o)
{
    constexpr int K   = (EPI == 1) ? 576 : (EPI == 3) ? 192 : 768;
    constexpr int nkb = K / 64;
    constexpr long sAz = (EPI == 1) ? 147456 : (EPI == 3) ? 147456 : 0;
    constexpr long sBz = (EPI == 0) ? 442368 : (EPI == 1) ? 110592 :
                         (EPI == 2) ? 147456 : (EPI == 3) ? 0 : 442368;

    const __nv_bfloat16* Aop =
        (EPI == 0) ? g_wqkv : (EPI == 1) ? g_attn : (EPI == 2) ? g_woimg :
        (EPI == 3) ? g_T : (EPI == 4) ? g_wfc1 : g_wfc2;
    const __nv_bfloat16* Bop =
        (EPI == 0) ? g_lnimgT : (EPI == 1) ? g_v : (EPI == 2) ? g_imgT :
        (EPI == 3) ? g_woimg2 : (EPI == 4) ? g_lnoutT : g_z2T;

    extern __shared__ __align__(16) char sm[];
    uint32_t sbase = smem_u32(sm);

    int tid = threadIdx.x, lane = tid & 31, wid = tid >> 5;
    int wm = wid & 3, wn = wid >> 2;
    int z = blockIdx.z, m0 = blockIdx.y * 128, n0 = blockIdx.x * 96;
    const __nv_bfloat16* Ab = Aop + sAz * z + (long)m0 * K;
    const __nv_bfloat16* Bb = Bop + sBz * z + (long)n0 * K;

    float acc[2][6][4];
    #pragma unroll
    for (int i = 0; i < 2; i++)
        #pragma unroll
        for (int j = 0; j < 6; j++)
            #pragma unroll
            for (int k = 0; k < 4; k++) acc[i][j][k] = 0.f;

    auto load_stage = [&](int slot, int kblk) {
        uint32_t sd = sbase + slot * STAGEB;
        const __nv_bfloat16* Akp = Ab + kblk * 64;
        const __nv_bfloat16* Bkp = Bb + kblk * 64;
        #pragma unroll
        for (int it = 0; it < 7; it++) {
            int i = tid + it * 256;
            int row = i >> 3, ch = i & 7;
            const __nv_bfloat16* src = (row < 128)
                ? (Akp + (long)row * K + ch * 8)
                : (Bkp + (long)(row - 128) * K + ch * 8);
            CPA16(sd + row * ASTRIDE + ch * 16, src);
        }
    };

    auto ldfrag = [&](uint32_t abase, uint32_t bbase, int s,
                      uint32_t (&fa)[2][4], uint32_t (&fb)[3][4]) {
        #pragma unroll
        for (int mi = 0; mi < 2; mi++) {
            uint32_t addr = abase + (mi * 16 + (lane & 15)) * ASTRIDE
                          + s * 32 + (lane >> 4) * 16;
            LDSM4(fa[mi][0], fa[mi][1], fa[mi][2], fa[mi][3], addr);
        }
        #pragma unroll
        for (int j = 0; j < 3; j++) {
            int nrow = j * 16 + (lane & 7) + ((lane >> 4) & 1) * 8;
            uint32_t addr = bbase + nrow * ASTRIDE + s * 32 + ((lane >> 3) & 1) * 16;
            LDSM4(fb[j][0], fb[j][1], fb[j][2], fb[j][3], addr);
        }
    };
    auto domma = [&](uint32_t (&fa)[2][4], uint32_t (&fb)[3][4]) {
        #pragma unroll
        for (int mi = 0; mi < 2; mi++)
            #pragma unroll
            for (int ni = 0; ni < 6; ni++)
                MMA16816(acc[mi][ni], fa[mi], fb[ni >> 1][(ni & 1) * 2], fb[ni >> 1][(ni & 1) * 2 + 1]);
    };

    load_stage(0, 0); CP_COMMIT();
    load_stage(1, 1); CP_COMMIT();
    CP_WAIT1();                  // buf0 arrived (g1 still pending)
    __syncthreads();             // visibility

    uint32_t fa0[2][4], fb0[3][4], fa1[2][4], fb1[3][4];
    {
        uint32_t ab = sbase + (wm * 32) * ASTRIDE;
        uint32_t bb = sbase + 128 * ASTRIDE + (wn * 48) * ASTRIDE;
        ldfrag(ab, bb, 0, fa0, fb0);
        ldfrag(ab, bb, 1, fa1, fb1);
    }

    for (int kb = 0; kb < nkb; kb++) {
        int buf = kb % 3;
        uint32_t ab = sbase + buf * STAGEB + (wm * 32) * ASTRIDE;
        uint32_t bb = sbase + buf * STAGEB + 128 * ASTRIDE + (wn * 48) * ASTRIDE;
        domma(fa0, fb0);                 // s0
        ldfrag(ab, bb, 2, fa0, fb0);
        domma(fa1, fb1);                 // s1
        ldfrag(ab, bb, 3, fa1, fb1);
        domma(fa0, fb0);                 // s2
        if (kb + 1 < nkb) {
            CP_WAIT0();                  // buf kb+1 data arrived
            __syncthreads();             // reads of buf kb done in all warps; visibility
            if (kb + 2 < nkb) { load_stage((kb + 2) % 3, kb + 2); CP_COMMIT(); }
            int nbuf = (kb + 1) % 3;
            uint32_t nab = sbase + nbuf * STAGEB + (wm * 32) * ASTRIDE;
            uint32_t nbb = sbase + nbuf * STAGEB + 128 * ASTRIDE + (wn * 48) * ASTRIDE;
            ldfrag(nab, nbb, 0, fa0, fb0);   // next s0 — overlaps s3 MMAs below
            domma(fa1, fb1);                 // s3 (fragments loaded pre-barrier)
            ldfrag(nab, nbb, 1, fa1, fb1);   // next s1
        } else {
            domma(fa1, fb1);                 // s3 final
        }
    }

    // ---------------- epilogue ----------------
    if (EPI == 1) {
        CP_WAIT0();
        __syncthreads();
        __nv_bfloat16* st = (__nv_bfloat16*)sm;
        #pragma unroll
        for (int mi = 0; mi < 2; mi++)
            #pragma unroll
            for (int ni = 0; ni < 6; ni++) {
                int cl = wn * 48 + ni * 8 + 2 * (lane & 3);
                #pragma unroll
                for (int h = 0; h < 2; h++) {
                    int rl = wm * 32 + mi * 16 + (lane >> 2) + h * 8;
                    st[cl * 136 + rl]       = __float2bfloat16(acc[mi][ni][h * 2]);
                    st[(cl + 1) * 136 + rl] = __float2bfloat16(acc[mi][ni][h * 2 + 1]);
                }
            }
        __syncthreads();
        int bz = z >> 2, nh = z & 3;
        int hvalid = (m0 == 0) ? 128 : 64;
        for (int task = tid; task < 96 * 16; task += 256) {
            int cc = task >> 4, h0 = (task & 15) * 8;
            if (h0 < hvalid) {
                uint4 v = *(uint4*)&st[cc * 136 + h0];
                long dst = (long)bz * 147456 + (long)(n0 + cc) * 768 + nh * 192 + m0 + h0;
                *(uint4*)(g_imgT + dst) = v;
            }
        }
        return;
    }

    const int mrow = m0 + wm * 32;
    const int ncol = n0 + wn * 48;
    #pragma unroll
    for (int mi = 0; mi < 2; mi++) {
        #pragma unroll
        for (int ni = 0; ni < 6; ni++) {
            int c = ncol + ni * 8 + 2 * (lane & 3);
            #pragma unroll
            for (int h = 0; h < 2; h++) {
                int r = mrow + mi * 16 + (lane >> 2) + h * 8;
                float f0 = acc[mi][ni][h * 2], f1 = acc[mi][ni][h * 2 + 1];
                if (EPI == 0) {
                    __nv_bfloat162 v;
                    v.x = __float2bfloat16(f0); v.y = __float2bfloat16(f1);
                    if (r < 1536)
                        *(__nv_bfloat162*)(g_qkb + (long)z * 884736 + (long)r * 576 + c) = v;
                    else
                        *(__nv_bfloat162*)(g_v + (long)z * 442368 + (long)(r - 1536) * 576 + c) = v;
                } else if (EPI == 2) {
                    __nv_bfloat162 v;
                    v.x = __float2bfloat16(f0); v.y = __float2bfloat16(f1);
                    *(__nv_bfloat162*)(g_T + (long)z * 147456 + (long)r * 192 + c) = v;
                } else if (EPI == 3) {
                    long o = (long)z * 442368 + (long)r * 576 + c;
                    float bm = biasM[r], rsum = g_rsumWo[r];
                    float2 rv = *(const float2*)(resExt + o);
                    float2 v = { f0 + bm + rsum * biasN[c] + rv.x,
                                 f1 + bm + rsum * biasN[c + 1] + rv.y };
                    *(float2*)(g_out + o) = v;
                } else if (EPI == 4) {
                    __nv_bfloat162 v;
                    v.x = __float2bfloat16(f0); v.y = __float2bfloat16(f1);
                    *(__nv_bfloat162*)(g_z1 + (long)z * 442368 + (long)r * 576 + c) = v;
                } else {
                    long o = (long)z * 442368 + (long)r * 576 + c;
                    float2 rv = *(const float2*)(g_out + o);
                    float2 v = { f0 + rv.x, f1 + rv.y };
                    *(float2*)(f32o + o) = v;
                }
            }
        }
    }
}

// ---------------- host launch --------------------------------------------------
extern "C" void kernel_launch(void* const* d_in, const int* in_sizes, int n_in,
                              void* d_out, int out_size) {
    const float* img    = (const float*)d_in[0];
    const float* txt    = (const float*)d_in[1];
    const float* fn_w   = (const float*)d_in[2];
    const float* fn_b   = (const float*)d_in[3];
    const float* gn_w   = (const float*)d_in[4];
    const float* gn_b   = (const float*)d_in[5];
    const float* qkv_img_w = (const float*)d_in[6];
    const float* qkv_txt_w = (const float*)d_in[7];
    const float* o_img_w   = (const float*)d_in[8];
    const float* o_img_b   = (const float*)d_in[9];
    const float* o_img2_w  = (const float*)d_in[10];
    const float* o_img2_b  = (const float*)d_in[11];
    const float* ffn_w  = (const float*)d_in[12];
    const float* ffn_b  = (const float*)d_in[13];
    const float* fc1_w  = (const float*)d_in[14];
    const float* dw_w   = (const float*)d_in[15];
    const float* fc2_w  = (const float*)d_in[16];
    float* out_p = (float*)d_out;

    const int SMEM = 3 * STAGEB;  // 96768
    cudaFuncSetAttribute(mm_gemm<0>, cudaFuncAttributeMaxDynamicSharedMemorySize, SMEM);
    cudaFuncSetAttribute(mm_gemm<1>, cudaFuncAttributeMaxDynamicSharedMemorySize, SMEM);
    cudaFuncSetAttribute(mm_gemm<2>, cudaFuncAttributeMaxDynamicSharedMemorySize, SMEM);
    cudaFuncSetAttribute(mm_gemm<3>, cudaFuncAttributeMaxDynamicSharedMemorySize, SMEM);
    cudaFuncSetAttribute(mm_gemm<4>, cudaFuncAttributeMaxDynamicSharedMemorySize, SMEM);
    cudaFuncSetAttribute(mm_gemm<5>, cudaFuncAttributeMaxDynamicSharedMemorySize, SMEM);

    castall_k<<<3564, 256>>>(qkv_img_w, o_img_w, o_img2_w, fc1_w, fc2_w);
    rowsum_k<<<96, 256>>>(o_img_w);
    txt_k<<<32, 256>>>(txt, gn_w, gn_b, qkv_txt_w);
    lnfT_k<0><<<dim3(18, 32), 256>>>(img, fn_w, fn_b);

    // qkv projection: M=2304, N=576, K=768
    mm_gemm<0><<<dim3(6, 18, 32), 256, SMEM>>>(nullptr, nullptr, nullptr, nullptr);
    attn_k<<<3072, 256>>>();
    // (attn1+attn2) @ V^T -> imgT: M=256(pad), N=192, K=576, batch=128
    mm_gemm<1><<<dim3(2, 2, 128), 256, SMEM>>>(nullptr, nullptr, nullptr, nullptr);
    // T = Wo @ img^T: M=768, N=192, K=768
    mm_gemm<2><<<dim3(2, 6, 32), 256, SMEM>>>(nullptr, nullptr, nullptr, nullptr);
    // out = T @ W2^T + bO + rsumWo*b2 + img: M=768, N=576, K=192
    mm_gemm<3><<<dim3(6, 6, 32), 256, SMEM>>>(o_img_b, o_img2_b, img, nullptr);
    lnfT_k<1><<<dim3(18, 32), 256>>>(nullptr, ffn_w, ffn_b);
    // fc1: M=768, N=576, K=768
    mm_gemm<4><<<dim3(6, 6, 32), 256, SMEM>>>(nullptr, nullptr, nullptr, nullptr);
    dwgelu2_k<<<B_ * 96, 256>>>(dw_w);
    // fc2 + residual(g_out) -> d_out
    mm_gemm<5><<<dim3(6, 6, 32), 256, SMEM>>>(nullptr, nullptr, nullptr, out_p);
}